// round 9
// baseline (speedup 1.0000x reference)
#include <cuda_runtime.h>
#include <math.h>
#include <stdint.h>

#define B_    128
#define SEQ_  200
#define VOCAB_ 1400
#define D_    256
#define H_    256
#define NCLS_ 128
#define G4H   1024

// ---------------- scratch (static __device__, no allocations) ----------------
__device__ float g_embedded[B_ * SEQ_ * D_];
__device__ float g_ux1[B_ * SEQ_ * G4H];
__device__ float g_ux2[B_ * SEQ_ * G4H];
__device__ float g_out1[B_ * SEQ_ * H_];
__device__ float g_out2[B_ * SEQ_ * H_];
__device__ float g_beta[B_ * SEQ_ * H_];
__device__ float g_hbuf[2 * 2 * B_ * H_];     // [lstm][parity][b][h]
__device__ float g_cbuf[2 * 2 * B_ * H_];
__device__ float g_alpha[B_ * SEQ_];
__device__ float g_ctx[B_ * D_];

// ---------------- packed fp32 helpers (sm_103a f32x2 pipe) ----------------
__device__ __forceinline__ void fma2(unsigned long long& d, unsigned long long a, unsigned long long b) {
    asm("fma.rn.f32x2 %0, %1, %2, %0;" : "+l"(d) : "l"(a), "l"(b));
}
__device__ __forceinline__ unsigned long long dup2(float v) {
    unsigned long long r;
    asm("mov.b64 %0, {%1, %1};" : "=l"(r) : "f"(v));
    return r;
}
__device__ __forceinline__ float2 unpack2(unsigned long long v) {
    float2 f;
    asm("mov.b64 {%0, %1}, %2;" : "=f"(f.x), "=f"(f.y) : "l"(v));
    return f;
}

// ---------------- generic fp32 tiled GEMM (f32x2, pre-duplicated B) ----------------
#define GBM 128
#define GBN 64
#define GBK 16
#define BSTR 68     // Bs row stride in ulonglongs (544B = 16B multiple, 8-bank shift)

template <bool BT>
__global__ void gemm_kernel(const float* __restrict__ A, const float* __restrict__ Bm,
                            float* __restrict__ C, int M, int N, int K,
                            const float* __restrict__ bias0, const float* __restrict__ bias1)
{
    __shared__ float As[GBK][GBM + 4];
    __shared__ alignas(16) unsigned long long Bs[GBK][BSTR];

    const int tid   = threadIdx.x;       // 256 threads
    const int m_blk = blockIdx.y * GBM;
    const int n_blk = blockIdx.x * GBN;
    const int tx = tid & 15;
    const int ty = tid >> 4;
    const int m0 = ty * 8;
    const int n0 = tx * 4;

    unsigned long long acc2[4][4];
#pragma unroll
    for (int i = 0; i < 4; i++)
#pragma unroll
        for (int j = 0; j < 4; j++) acc2[i][j] = 0ULL;

    const int a_row = tid >> 2;
    const int a_c4  = (tid & 3) * 4;

    for (int k0 = 0; k0 < K; k0 += GBK) {
#pragma unroll
        for (int r = 0; r < 2; r++) {
            int m = a_row + r * 64;
            float4 v = make_float4(0.f, 0.f, 0.f, 0.f);
            if (k0 + a_c4 < K)
                v = *reinterpret_cast<const float4*>(A + (size_t)(m_blk + m) * K + k0 + a_c4);
            As[a_c4 + 0][m] = v.x;
            As[a_c4 + 1][m] = v.y;
            As[a_c4 + 2][m] = v.z;
            As[a_c4 + 3][m] = v.w;
        }
        if (BT) {
            int n  = tid >> 2;
            int c4 = (tid & 3) * 4;
            float4 v = make_float4(0.f, 0.f, 0.f, 0.f);
            if (k0 + c4 < K)
                v = *reinterpret_cast<const float4*>(Bm + (size_t)(n_blk + n) * K + k0 + c4);
            Bs[c4 + 0][n] = dup2(v.x);
            Bs[c4 + 1][n] = dup2(v.y);
            Bs[c4 + 2][n] = dup2(v.z);
            Bs[c4 + 3][n] = dup2(v.w);
        } else {
            int kk = tid >> 4;
            int nn = (tid & 15) * 4;
            float4 v = make_float4(0.f, 0.f, 0.f, 0.f);
            if (k0 + kk < K)
                v = *reinterpret_cast<const float4*>(Bm + (size_t)(k0 + kk) * N + n_blk + nn);
            Bs[kk][nn + 0] = dup2(v.x);
            Bs[kk][nn + 1] = dup2(v.y);
            Bs[kk][nn + 2] = dup2(v.z);
            Bs[kk][nn + 3] = dup2(v.w);
        }
        __syncthreads();

#pragma unroll
        for (int kk = 0; kk < GBK; kk++) {
            const ulonglong2* ap = reinterpret_cast<const ulonglong2*>(&As[kk][m0]);
            ulonglong2 aA = ap[0];
            ulonglong2 aB = ap[1];
            const ulonglong2* bp = reinterpret_cast<const ulonglong2*>(&Bs[kk][n0]);
            ulonglong2 b01 = bp[0];
            ulonglong2 b23 = bp[1];
            unsigned long long bd[4] = {b01.x, b01.y, b23.x, b23.y};
            unsigned long long P[4] = {aA.x, aA.y, aB.x, aB.y};
#pragma unroll
            for (int p = 0; p < 4; p++)
#pragma unroll
                for (int j = 0; j < 4; j++) fma2(acc2[p][j], P[p], bd[j]);
        }
        __syncthreads();
    }

    float bv[4] = {0.f, 0.f, 0.f, 0.f};
    if (bias0) {
#pragma unroll
        for (int j = 0; j < 4; j++) bv[j] += bias0[n_blk + n0 + j];
    }
    if (bias1) {
#pragma unroll
        for (int j = 0; j < 4; j++) bv[j] += bias1[n_blk + n0 + j];
    }
#pragma unroll
    for (int p = 0; p < 4; p++) {
        float2 r0 = unpack2(acc2[p][0]);
        float2 r1 = unpack2(acc2[p][1]);
        float2 r2 = unpack2(acc2[p][2]);
        float2 r3 = unpack2(acc2[p][3]);
        float4 oA = make_float4(r0.x + bv[0], r1.x + bv[1], r2.x + bv[2], r3.x + bv[3]);
        float4 oB = make_float4(r0.y + bv[0], r1.y + bv[1], r2.y + bv[2], r3.y + bv[3]);
        *reinterpret_cast<float4*>(C + (size_t)(m_blk + m0 + 2 * p) * N + n_blk + n0)     = oA;
        *reinterpret_cast<float4*>(C + (size_t)(m_blk + m0 + 2 * p + 1) * N + n_blk + n0) = oB;
    }
}

// ---------------- init recurrent state ----------------
__global__ void init_state_kernel(const float* __restrict__ h01, const float* __restrict__ c01,
                                  const float* __restrict__ h02, const float* __restrict__ c02)
{
    int i = blockIdx.x * blockDim.x + threadIdx.x;
    if (i >= B_ * H_) return;
    g_hbuf[(0 * 2 + 0) * B_ * H_ + i] = h01[i];
    g_cbuf[(0 * 2 + 0) * B_ * H_ + i] = c01[i];
    g_hbuf[(1 * 2 + 0) * B_ * H_ + i] = h02[i];
    g_cbuf[(1 * 2 + 0) * B_ * H_ + i] = c02[i];
}

// ---------------- persistent LSTM scan: R3 structure + mbarrier cluster sync ----------------
// grid = 128 blocks = 16 clusters x 8. Cluster = (lstm, btile); rank = jtile.
// h/c exchanged through global double buffers (R3-proven); per-step sync via
// count-8 smem mbarrier (release/acquire at cluster scope — no fences, no L1 flush).
#define WJT 32
#define HS_STRIDE 260
#define MBAR_OFF (5 * WJT * 256 + 2 * 16 * HS_STRIDE)      // floats
#define SCAN_SMEM ((MBAR_OFF + 16) * 4)

__device__ __forceinline__ uint32_t smem_u32(const void* p) {
    uint32_t a;
    asm("{ .reg .u64 t; cvta.to.shared.u64 t, %1; cvt.u32.u64 %0, t; }" : "=r"(a) : "l"(p));
    return a;
}

__global__ __cluster_dims__(8, 1, 1) __launch_bounds__(256) void lstm_scan_kernel(
    const float* __restrict__ Wall1, const float* __restrict__ Wd1, const float* __restrict__ Wdb1,
    const float* __restrict__ Wall2, const float* __restrict__ Wd2, const float* __restrict__ Wdb2,
    const float* __restrict__ tsp)
{
    extern __shared__ float sm[];
    float* wsm = sm;                           // [5][32][256]
    float* hsm = sm + 5 * WJT * 256;           // [16][260]
    float* csm = hsm + 16 * HS_STRIDE;         // [16][260]
    const uint32_t mbar = smem_u32(sm + MBAR_OFF);

    const int bid   = blockIdx.x;
    const int lstm  = bid >> 6;
    const int btile = (bid >> 3) & 7;
    const int jt    = bid & 7;                 // == cluster rank
    const int b0 = btile * 16;
    const int j0 = jt * WJT;

    const float* Wall = lstm ? Wall2 : Wall1;
    const float* Wd   = lstm ? Wd2   : Wd1;
    const float* Wdb  = lstm ? Wdb2  : Wdb1;
    const float* ux   = lstm ? g_ux2 : g_ux1;
    float*       outp = lstm ? g_out2 : g_out1;

    const int tid = threadIdx.x;

    // ---- init mbarrier (count 8: one arrival from each cluster CTA) ----
    if (tid == 0) {
        asm volatile("mbarrier.init.shared.b64 [%0], 8;" :: "r"(mbar) : "memory");
    }
    __syncthreads();
    // one-time cluster barrier so all mbarriers are initialized before any arrive
    asm volatile("barrier.cluster.arrive.aligned;" ::: "memory");

    // ---- stage weights once ----
    for (int idx = tid; idx < 5 * WJT * 64; idx += 256) {
        int g   = idx >> 11;
        int rem = idx & 2047;
        int lj  = rem >> 6;
        int k4  = (rem & 63) << 2;
        const float* src = (g < 4) ? (Wall + (size_t)(g * H_ + j0 + lj) * H_ + k4)
                                   : (Wd   + (size_t)(j0 + lj) * H_ + k4);
        *reinterpret_cast<float4*>(&wsm[((g << 5) + lj) * 256 + k4]) =
            *reinterpret_cast<const float4*>(src);
    }

    const int bi = tid & 15;
    const int jj = tid >> 4;           // 0..15
    const int b  = b0 + bi;
    const int jA = j0 + jj;
    const int jB = jA + 16;
    const float wdbA = Wdb[jA];
    const float wdbB = Wdb[jB];

    const float* wA[5];
    const float* wB[5];
#pragma unroll
    for (int g = 0; g < 5; g++) {
        wA[g] = &wsm[((g << 5) + jj) * 256];
        wB[g] = &wsm[((g << 5) + jj + 16) * 256];
    }

    asm volatile("barrier.cluster.wait.aligned;" ::: "memory");

    for (int s = 0; s < SEQ_; s++) {
        const int pr = s & 1;
        const float* hsrc = g_hbuf + (size_t)(lstm * 2 + pr) * B_ * H_;
        const float* csrc = g_cbuf + (size_t)(lstm * 2 + pr) * B_ * H_;
        for (int idx = tid; idx < 16 * 64; idx += 256) {
            int r  = idx >> 6;
            int c4 = (idx & 63) << 2;
            *reinterpret_cast<float4*>(&hsm[r * HS_STRIDE + c4]) =
                *reinterpret_cast<const float4*>(&hsrc[(size_t)(b0 + r) * H_ + c4]);
            *reinterpret_cast<float4*>(&csm[r * HS_STRIDE + c4]) =
                *reinterpret_cast<const float4*>(&csrc[(size_t)(b0 + r) * H_ + c4]);
        }
        __syncthreads();

        // per-thread step inputs (prefetched; hidden under dot loop)
        const size_t row = (size_t)b * SEQ_ + s;
        const float t = tsp[row];
        const float* uxp = ux + row * G4H;
        float uxA[4], uxB[4];
#pragma unroll
        for (int g = 0; g < 4; g++) { uxA[g] = uxp[g * H_ + jA]; uxB[g] = uxp[g * H_ + jB]; }

        unsigned long long acc[10];
#pragma unroll
        for (int i = 0; i < 10; i++) acc[i] = 0ULL;
        const float* hrow = &hsm[bi * HS_STRIDE];
        const float* crow = &csm[bi * HS_STRIDE];

#pragma unroll 4
        for (int k = 0; k < H_; k += 4) {
            ulonglong2 h2 = *reinterpret_cast<const ulonglong2*>(&hrow[k]);
            ulonglong2 c2 = *reinterpret_cast<const ulonglong2*>(&crow[k]);
#pragma unroll
            for (int g = 0; g < 4; g++) {
                ulonglong2 w2 = *reinterpret_cast<const ulonglong2*>(&wA[g][k]);
                fma2(acc[g], h2.x, w2.x);
                fma2(acc[g], h2.y, w2.y);
                ulonglong2 v2 = *reinterpret_cast<const ulonglong2*>(&wB[g][k]);
                fma2(acc[5 + g], h2.x, v2.x);
                fma2(acc[5 + g], h2.y, v2.y);
            }
            ulonglong2 d2 = *reinterpret_cast<const ulonglong2*>(&wA[4][k]);
            fma2(acc[4], c2.x, d2.x);
            fma2(acc[4], c2.y, d2.y);
            ulonglong2 e2 = *reinterpret_cast<const ulonglong2*>(&wB[4][k]);
            fma2(acc[9], c2.x, e2.x);
            fma2(acc[9], c2.y, e2.y);
        }

        float* hdst = g_hbuf + (size_t)(lstm * 2 + (1 - pr)) * B_ * H_;
        float* cdst = g_cbuf + (size_t)(lstm * 2 + (1 - pr)) * B_ * H_;
#pragma unroll
        for (int half = 0; half < 2; half++) {
            const int base = half * 5;
            float2 vf = unpack2(acc[base + 0]);
            float2 vi = unpack2(acc[base + 1]);
            float2 vo = unpack2(acc[base + 2]);
            float2 vc = unpack2(acc[base + 3]);
            float2 vd = unpack2(acc[base + 4]);
            const float af = vf.x + vf.y;
            const float ai = vi.x + vi.y;
            const float ao = vo.x + vo.y;
            const float ag = vc.x + vc.y;
            const float ad = vd.x + vd.y;
            const int   j   = half ? jB : jA;
            const float wdb = half ? wdbB : wdbA;
            const float* uxv = half ? uxB : uxA;

            const float cs1  = tanhf(ad + wdb);
            const float ccur = crow[j];
            const float cadj = ccur - cs1 + cs1 * t;
            const float gf = 1.f / (1.f + expf(-(af + uxv[0])));
            const float gi = 1.f / (1.f + expf(-(ai + uxv[1])));
            const float go = 1.f / (1.f + expf(-(ao + uxv[2])));
            const float gc = 1.f / (1.f + expf(-(ag + uxv[3])));
            const float cnew = gf * cadj + gi * gc;
            const float hnew = go * tanhf(cnew);

            hdst[(size_t)b * H_ + j] = hnew;
            cdst[(size_t)b * H_ + j] = cnew;
            outp[row * H_ + j] = hnew;
        }

        // ---- per-step cluster sync via mbarrier (release/acquire, no fences) ----
        if (s + 1 < SEQ_) {
            __syncthreads();                   // all CTA stores issued before arrive
            if (tid < 8) {
                uint32_t remote;
                asm("mapa.shared::cluster.u32 %0, %1, %2;" : "=r"(remote) : "r"(mbar), "r"(tid));
                asm volatile("mbarrier.arrive.release.cluster.shared::cluster.b64 _, [%0];"
                             :: "r"(remote) : "memory");
            }
            // all threads wait on local barrier, phase parity = s & 1
            {
                const uint32_t par = (uint32_t)(s & 1);
                uint32_t done;
                asm volatile("{\n\t.reg .pred p;\n\t"
                    "mbarrier.try_wait.parity.acquire.cluster.shared::cta.b64 p, [%1], %2;\n\t"
                    "selp.b32 %0, 1, 0, p;\n\t}" : "=r"(done) : "r"(mbar), "r"(par) : "memory");
                if (!done) {
                    asm volatile("{\n\t.reg .pred P1;\n\t"
                        "WL_%=:\n\t"
                        "mbarrier.try_wait.parity.acquire.cluster.shared::cta.b64 P1, [%0], %1, 0x989680;\n\t"
                        "@P1 bra.uni WD_%=;\n\t"
                        "bra.uni WL_%=;\n\t"
                        "WD_%=:\n\t}" :: "r"(mbar), "r"(par) : "memory");
                }
            }
            __syncthreads();
        }
    }
}

// ---------------- attention softmax ----------------
__global__ void attn_softmax_kernel(const float* __restrict__ wa)
{
    const int b    = blockIdx.x;
    const int tid  = threadIdx.x;
    const int lane = tid & 31;
    const int w    = tid >> 5;
    __shared__ float Es[SEQ_];
    __shared__ float mx, smv;

    for (int s = w; s < SEQ_; s += 8) {
        const float* o = g_out1 + ((size_t)b * SEQ_ + s) * H_;
        float sum = 0.f;
        for (int h = lane; h < H_; h += 32) sum += o[h] * wa[h];
#pragma unroll
        for (int off = 16; off; off >>= 1) sum += __shfl_xor_sync(0xffffffffu, sum, off);
        if (lane == 0) Es[s] = sum;
    }
    __syncthreads();
    if (tid == 0) {
        float m = -1e30f;
        for (int s = 0; s < SEQ_; s++) m = fmaxf(m, Es[s]);
        mx = m;
    }
    __syncthreads();
    if (tid < SEQ_) Es[tid] = expf(Es[tid] - mx);
    __syncthreads();
    if (tid == 0) {
        float t = 0.f;
        for (int s = 0; s < SEQ_; s++) t += Es[s];
        smv = t;
    }
    __syncthreads();
    if (tid < SEQ_) g_alpha[(size_t)b * SEQ_ + tid] = Es[tid] / smv;
}

// ---------------- ctx ----------------
__global__ void ctx_kernel()
{
    const int b = blockIdx.x;
    const int d = threadIdx.x;
    float acc = 0.f;
    for (int s = 0; s < SEQ_; s++) {
        size_t r = (size_t)b * SEQ_ + s;
        acc += g_embedded[r * D_ + d] * tanhf(g_beta[r * H_ + d]) * g_alpha[r];
    }
    g_ctx[(size_t)b * D_ + d] = acc;
}

// ---------------- output head ----------------
__global__ void out_kernel(const float* __restrict__ Wout, float* __restrict__ out)
{
    const int b = blockIdx.x;
    const int n = threadIdx.x;
    __shared__ float cx[D_];
    for (int d = threadIdx.x; d < D_; d += blockDim.x) cx[d] = g_ctx[(size_t)b * D_ + d];
    __syncthreads();
    float acc = 0.f;
    const float* wr = Wout + (size_t)n * H_;
#pragma unroll 8
    for (int d = 0; d < D_; d++) acc = fmaf(cx[d], wr[d], acc);
    out[(size_t)b * NCLS_ + n] = acc;
}

// ---------------- host launcher ----------------
extern "C" void kernel_launch(void* const* d_in, const int* in_sizes, int n_in,
                              void* d_out, int out_size)
{
    const float* inputs = (const float*)d_in[0];
    const float* tsp    = (const float*)d_in[1];
    const float* emb    = (const float*)d_in[2];
    const float* Wall1  = (const float*)d_in[3];
    const float* Wall1b = (const float*)d_in[4];
    const float* Uall1  = (const float*)d_in[5];
    const float* Uall1b = (const float*)d_in[6];
    const float* Wd1    = (const float*)d_in[7];
    const float* Wd1b   = (const float*)d_in[8];
    const float* Wall2  = (const float*)d_in[9];
    const float* Wall2b = (const float*)d_in[10];
    const float* Uall2  = (const float*)d_in[11];
    const float* Uall2b = (const float*)d_in[12];
    const float* Wd2    = (const float*)d_in[13];
    const float* Wd2b   = (const float*)d_in[14];
    const float* wa     = (const float*)d_in[15];
    const float* Wb     = (const float*)d_in[16];
    const float* Wout   = (const float*)d_in[17];
    const float* h01    = (const float*)d_in[18];
    const float* c01    = (const float*)d_in[19];
    const float* h02    = (const float*)d_in[20];
    const float* c02    = (const float*)d_in[21];
    float* out = (float*)d_out;

    void *p_emb, *p_ux1, *p_ux2, *p_out2, *p_beta;
    cudaGetSymbolAddress(&p_emb,  g_embedded);
    cudaGetSymbolAddress(&p_ux1,  g_ux1);
    cudaGetSymbolAddress(&p_ux2,  g_ux2);
    cudaGetSymbolAddress(&p_out2, g_out2);
    cudaGetSymbolAddress(&p_beta, g_beta);

    cudaFuncSetAttribute(lstm_scan_kernel,
                         cudaFuncAttributeMaxDynamicSharedMemorySize, SCAN_SMEM);

    const int M = B_ * SEQ_;   // 25600

    // 1) embedded = inputs @ emb
    gemm_kernel<false><<<dim3(D_ / GBN, M / GBM), 256>>>(
        inputs, emb, (float*)p_emb, M, D_, VOCAB_, nullptr, nullptr);

    // 2) ux = embedded @ Uall^T + (Uall_b + Wall_b)
    gemm_kernel<true><<<dim3(G4H / GBN, M / GBM), 256>>>(
        (const float*)p_emb, Uall1, (float*)p_ux1, M, G4H, D_, Uall1b, Wall1b);
    gemm_kernel<true><<<dim3(G4H / GBN, M / GBM), 256>>>(
        (const float*)p_emb, Uall2, (float*)p_ux2, M, G4H, D_, Uall2b, Wall2b);

    // 3) recurrent scan — 16 clusters x 8 CTAs, mbarrier per-step sync
    init_state_kernel<<<(B_ * H_ + 255) / 256, 256>>>(h01, c01, h02, c02);
    lstm_scan_kernel<<<128, 256, SCAN_SMEM>>>(Wall1, Wd1, Wd1b, Wall2, Wd2, Wd2b, tsp);

    // 4) attention weights
    attn_softmax_kernel<<<B_, 256>>>(wa);

    // 5) beta = out2 @ Wb^T
    gemm_kernel<true><<<dim3(H_ / GBN, M / GBM), 256>>>(
        (const float*)p_out2, Wb, (float*)p_beta, M, H_, D_, nullptr, nullptr);

    // 6) context + output head
    ctx_kernel<<<B_, 256>>>();
    out_kernel<<<B_, 128>>>(Wout, out);
}

// round 10
// speedup vs baseline: 1.5769x; 1.5769x over previous
#include <cuda_runtime.h>
#include <math.h>
#include <stdint.h>

#define B_    128
#define SEQ_  200
#define VOCAB_ 1400
#define D_    256
#define H_    256
#define NCLS_ 128
#define G4H   1024

// ---------------- scratch (static __device__, no allocations) ----------------
__device__ float g_embedded[B_ * SEQ_ * D_];
__device__ float g_ux1[B_ * SEQ_ * G4H];
__device__ float g_ux2[B_ * SEQ_ * G4H];
__device__ float g_out1[B_ * SEQ_ * H_];
__device__ float g_out2[B_ * SEQ_ * H_];
__device__ float g_beta[B_ * SEQ_ * H_];
__device__ float g_hbuf[2 * 2 * B_ * H_];     // [lstm][parity][b][h]
__device__ float g_cbuf[2 * 2 * B_ * H_];
__device__ float g_alpha[B_ * SEQ_];
__device__ float g_ctx[B_ * D_];
__device__ unsigned g_cnt[16];
__device__ volatile unsigned g_gen[16];

// ---------------- packed fp32 helpers (sm_103a f32x2 pipe) ----------------
__device__ __forceinline__ void fma2(unsigned long long& d, unsigned long long a, unsigned long long b) {
    asm("fma.rn.f32x2 %0, %1, %2, %0;" : "+l"(d) : "l"(a), "l"(b));
}
__device__ __forceinline__ unsigned long long dup2(float v) {
    unsigned long long r;
    asm("mov.b64 %0, {%1, %1};" : "=l"(r) : "f"(v));
    return r;
}
__device__ __forceinline__ float2 unpack2(unsigned long long v) {
    float2 f;
    asm("mov.b64 {%0, %1}, %2;" : "=f"(f.x), "=f"(f.y) : "l"(v));
    return f;
}

// ---------------- fp32 tiled GEMM: 128x128 tile, conflict-free pre-dup B ----------------
// C[m][n] = sum_k A[m][k] * Bm (+ bias0[n] + bias1[n])
// BT=true : Bm is [N][K]   BT=false: Bm is [K][N]
// 256 threads, micro-tile 8m x 8n; n-values at {32q + 2tx, +1} for q=0..3
// (word-stride 4 per lane -> every LDS.128 phase hits 32 distinct banks).
#define GBM 128
#define GBN 128
#define GBK 16
#define ASTR 132           // As row stride in floats (528B, 16B multiple)
#define BSTR 132           // Bs row stride in ulonglongs (1056B, 16B multiple)

template <bool BT>
__global__ __launch_bounds__(256) void gemm_kernel(
    const float* __restrict__ A, const float* __restrict__ Bm,
    float* __restrict__ C, int M, int N, int K,
    const float* __restrict__ bias0, const float* __restrict__ bias1)
{
    __shared__ float As[GBK][ASTR];
    __shared__ alignas(16) unsigned long long Bs[GBK][BSTR];

    const int tid   = threadIdx.x;       // 256 threads
    const int m_blk = blockIdx.y * GBM;
    const int n_blk = blockIdx.x * GBN;
    const int tx = tid & 15;             // n index
    const int ty = tid >> 4;             // m index
    const int m0 = ty * 8;
    const int n2 = tx * 2;               // base n offset within each 32-wide quarter

    unsigned long long acc2[4][8];       // [m-pair p][q*2 + i]
#pragma unroll
    for (int p = 0; p < 4; p++)
#pragma unroll
        for (int j = 0; j < 8; j++) acc2[p][j] = 0ULL;

    const int a_row = tid >> 2;          // 0..63
    const int a_c4  = (tid & 3) * 4;

    for (int k0 = 0; k0 < K; k0 += GBK) {
        // ---- stage A (128 x 16, k-major) ----
#pragma unroll
        for (int r = 0; r < 2; r++) {
            int m = a_row + r * 64;
            float4 v = make_float4(0.f, 0.f, 0.f, 0.f);
            if (k0 + a_c4 < K)
                v = *reinterpret_cast<const float4*>(A + (size_t)(m_blk + m) * K + k0 + a_c4);
            As[a_c4 + 0][m] = v.x;
            As[a_c4 + 1][m] = v.y;
            As[a_c4 + 2][m] = v.z;
            As[a_c4 + 3][m] = v.w;
        }
        // ---- stage B (128 n x 16 k), pre-duplicated ----
        if (BT) {
            int n  = tid >> 1;           // 0..127
            int c8 = (tid & 1) * 8;
            const float* src = Bm + (size_t)(n_blk + n) * K + k0 + c8;
            float4 v0 = make_float4(0.f, 0.f, 0.f, 0.f);
            float4 v1 = make_float4(0.f, 0.f, 0.f, 0.f);
            if (k0 + c8 < K)     v0 = *reinterpret_cast<const float4*>(src);
            if (k0 + c8 + 4 < K) v1 = *reinterpret_cast<const float4*>(src + 4);
            Bs[c8 + 0][n] = dup2(v0.x);
            Bs[c8 + 1][n] = dup2(v0.y);
            Bs[c8 + 2][n] = dup2(v0.z);
            Bs[c8 + 3][n] = dup2(v0.w);
            Bs[c8 + 4][n] = dup2(v1.x);
            Bs[c8 + 5][n] = dup2(v1.y);
            Bs[c8 + 6][n] = dup2(v1.z);
            Bs[c8 + 7][n] = dup2(v1.w);
        } else {
            int kk = tid >> 4;           // 0..15
            int nn = (tid & 15) * 8;
            const float* src = Bm + (size_t)(k0 + kk) * N + n_blk + nn;
            float4 v0 = make_float4(0.f, 0.f, 0.f, 0.f);
            float4 v1 = make_float4(0.f, 0.f, 0.f, 0.f);
            if (k0 + kk < K) {
                v0 = *reinterpret_cast<const float4*>(src);
                v1 = *reinterpret_cast<const float4*>(src + 4);
            }
            Bs[kk][nn + 0] = dup2(v0.x);
            Bs[kk][nn + 1] = dup2(v0.y);
            Bs[kk][nn + 2] = dup2(v0.z);
            Bs[kk][nn + 3] = dup2(v0.w);
            Bs[kk][nn + 4] = dup2(v1.x);
            Bs[kk][nn + 5] = dup2(v1.y);
            Bs[kk][nn + 6] = dup2(v1.z);
            Bs[kk][nn + 7] = dup2(v1.w);
        }
        __syncthreads();

#pragma unroll
        for (int kk = 0; kk < GBK; kk++) {
            const ulonglong2* ap = reinterpret_cast<const ulonglong2*>(&As[kk][m0]);
            ulonglong2 aA = ap[0];
            ulonglong2 aB = ap[1];
            unsigned long long P[4] = {aA.x, aA.y, aB.x, aB.y};
            ulonglong2 bq0 = *reinterpret_cast<const ulonglong2*>(&Bs[kk][n2 + 0]);
            ulonglong2 bq1 = *reinterpret_cast<const ulonglong2*>(&Bs[kk][n2 + 32]);
            ulonglong2 bq2 = *reinterpret_cast<const ulonglong2*>(&Bs[kk][n2 + 64]);
            ulonglong2 bq3 = *reinterpret_cast<const ulonglong2*>(&Bs[kk][n2 + 96]);
            unsigned long long bd[8] = {bq0.x, bq0.y, bq1.x, bq1.y, bq2.x, bq2.y, bq3.x, bq3.y};
#pragma unroll
            for (int p = 0; p < 4; p++)
#pragma unroll
                for (int j = 0; j < 8; j++) fma2(acc2[p][j], P[p], bd[j]);
        }
        __syncthreads();
    }

    // ---- epilogue: 4 quarters x 4 m-pairs, float2 stores ----
#pragma unroll
    for (int q = 0; q < 4; q++) {
        const int col = n_blk + q * 32 + n2;
        float b0 = 0.f, b1 = 0.f;
        if (bias0) { b0 += bias0[col]; b1 += bias0[col + 1]; }
        if (bias1) { b0 += bias1[col]; b1 += bias1[col + 1]; }
#pragma unroll
        for (int p = 0; p < 4; p++) {
            float2 e0 = unpack2(acc2[p][q * 2 + 0]);   // col,   rows (lo, hi)
            float2 e1 = unpack2(acc2[p][q * 2 + 1]);   // col+1, rows (lo, hi)
            const int row0 = m_blk + m0 + 2 * p;
            *reinterpret_cast<float2*>(C + (size_t)row0 * N + col) =
                make_float2(e0.x + b0, e1.x + b1);
            *reinterpret_cast<float2*>(C + (size_t)(row0 + 1) * N + col) =
                make_float2(e0.y + b0, e1.y + b1);
        }
    }
}

// ---------------- init recurrent state + barriers (R3 verbatim) ----------------
__global__ void init_state_kernel(const float* __restrict__ h01, const float* __restrict__ c01,
                                  const float* __restrict__ h02, const float* __restrict__ c02)
{
    int i = blockIdx.x * blockDim.x + threadIdx.x;
    if (i < 16) { g_cnt[i] = 0; *((unsigned*)&g_gen[i]) = 0; }
    if (i >= B_ * H_) return;
    g_hbuf[(0 * 2 + 0) * B_ * H_ + i] = h01[i];
    g_cbuf[(0 * 2 + 0) * B_ * H_ + i] = c01[i];
    g_hbuf[(1 * 2 + 0) * B_ * H_ + i] = h02[i];
    g_cbuf[(1 * 2 + 0) * B_ * H_ + i] = c02[i];
}

// ---------------- persistent LSTM scan (R3 verbatim) ----------------
#define WJT 32
#define HS_STRIDE 260
#define SCAN_SMEM ((5 * WJT * 256 + 2 * 16 * HS_STRIDE) * 4)

__global__ __launch_bounds__(256) void lstm_scan_kernel(
    const float* __restrict__ Wall1, const float* __restrict__ Wd1, const float* __restrict__ Wdb1,
    const float* __restrict__ Wall2, const float* __restrict__ Wd2, const float* __restrict__ Wdb2,
    const float* __restrict__ tsp)
{
    extern __shared__ float sm[];
    float* wsm = sm;
    float* hsm = sm + 5 * WJT * 256;
    float* csm = hsm + 16 * HS_STRIDE;

    const int bid   = blockIdx.x;
    const int lstm  = bid >> 6;
    const int btile = (bid >> 3) & 7;
    const int jt    = bid & 7;
    const int b0 = btile * 16;
    const int j0 = jt * WJT;
    const int grp = lstm * 8 + btile;

    const float* Wall = lstm ? Wall2 : Wall1;
    const float* Wd   = lstm ? Wd2   : Wd1;
    const float* Wdb  = lstm ? Wdb2  : Wdb1;
    const float* ux   = lstm ? g_ux2 : g_ux1;
    float*       outp = lstm ? g_out2 : g_out1;

    const int tid = threadIdx.x;

    for (int idx = tid; idx < 5 * WJT * 64; idx += 256) {
        int g   = idx >> 11;
        int rem = idx & 2047;
        int lj  = rem >> 6;
        int k4  = (rem & 63) << 2;
        const float* src = (g < 4) ? (Wall + (size_t)(g * H_ + j0 + lj) * H_ + k4)
                                   : (Wd   + (size_t)(j0 + lj) * H_ + k4);
        *reinterpret_cast<float4*>(&wsm[((g << 5) + lj) * 256 + k4]) =
            *reinterpret_cast<const float4*>(src);
    }

    const int bi = tid & 15;
    const int jj = tid >> 4;
    const int b  = b0 + bi;
    const int jA = j0 + jj;
    const int jB = jA + 16;
    const float wdbA = Wdb[jA];
    const float wdbB = Wdb[jB];

    const float* wA[5];
    const float* wB[5];
#pragma unroll
    for (int g = 0; g < 5; g++) {
        wA[g] = &wsm[((g << 5) + jj) * 256];
        wB[g] = &wsm[((g << 5) + jj + 16) * 256];
    }

    for (int s = 0; s < SEQ_; s++) {
        const int pr = s & 1;
        const float* hsrc = g_hbuf + (size_t)(lstm * 2 + pr) * B_ * H_;
        const float* csrc = g_cbuf + (size_t)(lstm * 2 + pr) * B_ * H_;
        for (int idx = tid; idx < 16 * 64; idx += 256) {
            int r  = idx >> 6;
            int c4 = (idx & 63) << 2;
            *reinterpret_cast<float4*>(&hsm[r * HS_STRIDE + c4]) =
                *reinterpret_cast<const float4*>(&hsrc[(size_t)(b0 + r) * H_ + c4]);
            *reinterpret_cast<float4*>(&csm[r * HS_STRIDE + c4]) =
                *reinterpret_cast<const float4*>(&csrc[(size_t)(b0 + r) * H_ + c4]);
        }
        __syncthreads();

        const size_t row = (size_t)b * SEQ_ + s;
        const float t = tsp[row];
        const float* uxp = ux + row * G4H;
        float uxA[4], uxB[4];
#pragma unroll
        for (int g = 0; g < 4; g++) { uxA[g] = uxp[g * H_ + jA]; uxB[g] = uxp[g * H_ + jB]; }

        unsigned long long acc[10];
#pragma unroll
        for (int i = 0; i < 10; i++) acc[i] = 0ULL;
        const float* hrow = &hsm[bi * HS_STRIDE];
        const float* crow = &csm[bi * HS_STRIDE];

#pragma unroll 4
        for (int k = 0; k < H_; k += 4) {
            ulonglong2 h2 = *reinterpret_cast<const ulonglong2*>(&hrow[k]);
            ulonglong2 c2 = *reinterpret_cast<const ulonglong2*>(&crow[k]);
#pragma unroll
            for (int g = 0; g < 4; g++) {
                ulonglong2 w2 = *reinterpret_cast<const ulonglong2*>(&wA[g][k]);
                fma2(acc[g], h2.x, w2.x);
                fma2(acc[g], h2.y, w2.y);
                ulonglong2 v2 = *reinterpret_cast<const ulonglong2*>(&wB[g][k]);
                fma2(acc[5 + g], h2.x, v2.x);
                fma2(acc[5 + g], h2.y, v2.y);
            }
            ulonglong2 d2 = *reinterpret_cast<const ulonglong2*>(&wA[4][k]);
            fma2(acc[4], c2.x, d2.x);
            fma2(acc[4], c2.y, d2.y);
            ulonglong2 e2 = *reinterpret_cast<const ulonglong2*>(&wB[4][k]);
            fma2(acc[9], c2.x, e2.x);
            fma2(acc[9], c2.y, e2.y);
        }

        float* hdst = g_hbuf + (size_t)(lstm * 2 + (1 - pr)) * B_ * H_;
        float* cdst = g_cbuf + (size_t)(lstm * 2 + (1 - pr)) * B_ * H_;
#pragma unroll
        for (int half = 0; half < 2; half++) {
            const int base = half * 5;
            float2 vf = unpack2(acc[base + 0]);
            float2 vi = unpack2(acc[base + 1]);
            float2 vo = unpack2(acc[base + 2]);
            float2 vc = unpack2(acc[base + 3]);
            float2 vd = unpack2(acc[base + 4]);
            const float af = vf.x + vf.y;
            const float ai = vi.x + vi.y;
            const float ao = vo.x + vo.y;
            const float ag = vc.x + vc.y;
            const float ad = vd.x + vd.y;
            const int   j   = half ? jB : jA;
            const float wdb = half ? wdbB : wdbA;
            const float* uxv = half ? uxB : uxA;

            const float cs1  = tanhf(ad + wdb);
            const float ccur = crow[j];
            const float cadj = ccur - cs1 + cs1 * t;
            const float gf = 1.f / (1.f + expf(-(af + uxv[0])));
            const float gi = 1.f / (1.f + expf(-(ai + uxv[1])));
            const float go = 1.f / (1.f + expf(-(ao + uxv[2])));
            const float gc = 1.f / (1.f + expf(-(ag + uxv[3])));
            const float cnew = gf * cadj + gi * gc;
            const float hnew = go * tanhf(cnew);

            hdst[(size_t)b * H_ + j] = hnew;
            cdst[(size_t)b * H_ + j] = cnew;
            outp[row * H_ + j] = hnew;
        }

        __threadfence();
        __syncthreads();
        if (tid == 0) {
            unsigned arrived = atomicAdd(&g_cnt[grp], 1u);
            if (arrived == 7u) {
                g_cnt[grp] = 0;
                __threadfence();
                atomicAdd((unsigned*)&g_gen[grp], 1u);
            }
            while (g_gen[grp] < (unsigned)(s + 1)) { __nanosleep(32); }
        }
        __syncthreads();
        __threadfence();
    }
}

// ---------------- attention softmax ----------------
__global__ void attn_softmax_kernel(const float* __restrict__ wa)
{
    const int b    = blockIdx.x;
    const int tid  = threadIdx.x;
    const int lane = tid & 31;
    const int w    = tid >> 5;
    __shared__ float Es[SEQ_];
    __shared__ float mx, smv;

    for (int s = w; s < SEQ_; s += 8) {
        const float* o = g_out1 + ((size_t)b * SEQ_ + s) * H_;
        float sum = 0.f;
        for (int h = lane; h < H_; h += 32) sum += o[h] * wa[h];
#pragma unroll
        for (int off = 16; off; off >>= 1) sum += __shfl_xor_sync(0xffffffffu, sum, off);
        if (lane == 0) Es[s] = sum;
    }
    __syncthreads();
    if (tid == 0) {
        float m = -1e30f;
        for (int s = 0; s < SEQ_; s++) m = fmaxf(m, Es[s]);
        mx = m;
    }
    __syncthreads();
    if (tid < SEQ_) Es[tid] = expf(Es[tid] - mx);
    __syncthreads();
    if (tid == 0) {
        float t = 0.f;
        for (int s = 0; s < SEQ_; s++) t += Es[s];
        smv = t;
    }
    __syncthreads();
    if (tid < SEQ_) g_alpha[(size_t)b * SEQ_ + tid] = Es[tid] / smv;
}

// ---------------- ctx ----------------
__global__ void ctx_kernel()
{
    const int b = blockIdx.x;
    const int d = threadIdx.x;
    float acc = 0.f;
    for (int s = 0; s < SEQ_; s++) {
        size_t r = (size_t)b * SEQ_ + s;
        acc += g_embedded[r * D_ + d] * tanhf(g_beta[r * H_ + d]) * g_alpha[r];
    }
    g_ctx[(size_t)b * D_ + d] = acc;
}

// ---------------- output head ----------------
__global__ void out_kernel(const float* __restrict__ Wout, float* __restrict__ out)
{
    const int b = blockIdx.x;
    const int n = threadIdx.x;
    __shared__ float cx[D_];
    for (int d = threadIdx.x; d < D_; d += blockDim.x) cx[d] = g_ctx[(size_t)b * D_ + d];
    __syncthreads();
    float acc = 0.f;
    const float* wr = Wout + (size_t)n * H_;
#pragma unroll 8
    for (int d = 0; d < D_; d++) acc = fmaf(cx[d], wr[d], acc);
    out[(size_t)b * NCLS_ + n] = acc;
}

// ---------------- host launcher ----------------
extern "C" void kernel_launch(void* const* d_in, const int* in_sizes, int n_in,
                              void* d_out, int out_size)
{
    const float* inputs = (const float*)d_in[0];
    const float* tsp    = (const float*)d_in[1];
    const float* emb    = (const float*)d_in[2];
    const float* Wall1  = (const float*)d_in[3];
    const float* Wall1b = (const float*)d_in[4];
    const float* Uall1  = (const float*)d_in[5];
    const float* Uall1b = (const float*)d_in[6];
    const float* Wd1    = (const float*)d_in[7];
    const float* Wd1b   = (const float*)d_in[8];
    const float* Wall2  = (const float*)d_in[9];
    const float* Wall2b = (const float*)d_in[10];
    const float* Uall2  = (const float*)d_in[11];
    const float* Uall2b = (const float*)d_in[12];
    const float* Wd2    = (const float*)d_in[13];
    const float* Wd2b   = (const float*)d_in[14];
    const float* wa     = (const float*)d_in[15];
    const float* Wb     = (const float*)d_in[16];
    const float* Wout   = (const float*)d_in[17];
    const float* h01    = (const float*)d_in[18];
    const float* c01    = (const float*)d_in[19];
    const float* h02    = (const float*)d_in[20];
    const float* c02    = (const float*)d_in[21];
    float* out = (float*)d_out;

    void *p_emb, *p_ux1, *p_ux2, *p_out2, *p_beta;
    cudaGetSymbolAddress(&p_emb,  g_embedded);
    cudaGetSymbolAddress(&p_ux1,  g_ux1);
    cudaGetSymbolAddress(&p_ux2,  g_ux2);
    cudaGetSymbolAddress(&p_out2, g_out2);
    cudaGetSymbolAddress(&p_beta, g_beta);

    cudaFuncSetAttribute(lstm_scan_kernel,
                         cudaFuncAttributeMaxDynamicSharedMemorySize, SCAN_SMEM);

    const int M = B_ * SEQ_;   // 25600

    // 1) embedded = inputs @ emb      [25600 x 256], K=1400
    gemm_kernel<false><<<dim3(D_ / GBN, M / GBM), 256>>>(
        inputs, emb, (float*)p_emb, M, D_, VOCAB_, nullptr, nullptr);

    // 2) ux = embedded @ Uall^T + (Uall_b + Wall_b)   [25600 x 1024], K=256
    gemm_kernel<true><<<dim3(G4H / GBN, M / GBM), 256>>>(
        (const float*)p_emb, Uall1, (float*)p_ux1, M, G4H, D_, Uall1b, Wall1b);
    gemm_kernel<true><<<dim3(G4H / GBN, M / GBM), 256>>>(
        (const float*)p_emb, Uall2, (float*)p_ux2, M, G4H, D_, Uall2b, Wall2b);

    // 3) recurrent scan — R3 configuration, unchanged
    init_state_kernel<<<(B_ * H_ + 255) / 256, 256>>>(h01, c01, h02, c02);
    lstm_scan_kernel<<<128, 256, SCAN_SMEM>>>(Wall1, Wd1, Wd1b, Wall2, Wd2, Wd2b, tsp);

    // 4) attention weights
    attn_softmax_kernel<<<B_, 256>>>(wa);

    // 5) beta = out2 @ Wb^T   [25600 x 256], K=256
    gemm_kernel<true><<<dim3(H_ / GBN, M / GBM), 256>>>(
        (const float*)p_out2, Wb, (float*)p_beta, M, H_, D_, nullptr, nullptr);

    // 6) context + output head
    ctx_kernel<<<B_, 256>>>();
    out_kernel<<<B_, 128>>>(Wout, out);
}

// round 11
// speedup vs baseline: 1.8591x; 1.1789x over previous
#include <cuda_runtime.h>
#include <math.h>
#include <stdint.h>

#define B_    128
#define SEQ_  200
#define VOCAB_ 1400
#define D_    256
#define H_    256
#define NCLS_ 128
#define G4H   1024

// ---------------- scratch (static __device__, no allocations) ----------------
__device__ float g_embedded[B_ * SEQ_ * D_];
__device__ float g_ux1[B_ * SEQ_ * G4H];
__device__ float g_ux2[B_ * SEQ_ * G4H];
__device__ float g_out1[B_ * SEQ_ * H_];
__device__ float g_out2[B_ * SEQ_ * H_];
__device__ float g_beta[B_ * SEQ_ * H_];
__device__ float g_hbuf[2 * 2 * B_ * H_];     // [lstm][parity][b][h]
__device__ float g_cbuf[2 * 2 * B_ * H_];
__device__ float g_alpha[B_ * SEQ_];
__device__ float g_ctxp[4][B_ * D_];          // 4 partial ctx sums
__device__ unsigned g_cnt[16];                // monotonic per-group arrival counters

// ---------------- packed fp32 helpers (sm_103a f32x2 pipe) ----------------
__device__ __forceinline__ void fma2(unsigned long long& d, unsigned long long a, unsigned long long b) {
    asm("fma.rn.f32x2 %0, %1, %2, %0;" : "+l"(d) : "l"(a), "l"(b));
}
__device__ __forceinline__ unsigned long long dup2(float v) {
    unsigned long long r;
    asm("mov.b64 %0, {%1, %1};" : "=l"(r) : "f"(v));
    return r;
}
__device__ __forceinline__ float2 unpack2(unsigned long long v) {
    float2 f;
    asm("mov.b64 {%0, %1}, %2;" : "=f"(f.x), "=f"(f.y) : "l"(v));
    return f;
}

// ---------------- generic fp32 tiled GEMM (R3 verbatim — proven best) ----------------
#define GBM 128
#define GBN 64
#define GBK 16

template <bool BT>
__global__ void gemm_kernel(const float* __restrict__ A, const float* __restrict__ Bm,
                            float* __restrict__ C, int M, int N, int K,
                            const float* __restrict__ bias0, const float* __restrict__ bias1)
{
    __shared__ float As[GBK][GBM + 4];
    __shared__ float Bs[GBK][GBN + 4];

    const int tid   = threadIdx.x;       // 256 threads
    const int m_blk = blockIdx.y * GBM;
    const int n_blk = blockIdx.x * GBN;
    const int tx = tid & 15;
    const int ty = tid >> 4;
    const int m0 = ty * 8;
    const int n0 = tx * 4;

    unsigned long long acc2[4][4];
#pragma unroll
    for (int i = 0; i < 4; i++)
#pragma unroll
        for (int j = 0; j < 4; j++) acc2[i][j] = 0ULL;

    const int a_row = tid >> 2;
    const int a_c4  = (tid & 3) * 4;

    for (int k0 = 0; k0 < K; k0 += GBK) {
#pragma unroll
        for (int r = 0; r < 2; r++) {
            int m = a_row + r * 64;
            float4 v = make_float4(0.f, 0.f, 0.f, 0.f);
            if (k0 + a_c4 < K)
                v = *reinterpret_cast<const float4*>(A + (size_t)(m_blk + m) * K + k0 + a_c4);
            As[a_c4 + 0][m] = v.x;
            As[a_c4 + 1][m] = v.y;
            As[a_c4 + 2][m] = v.z;
            As[a_c4 + 3][m] = v.w;
        }
        if (BT) {
            int n  = tid >> 2;
            int c4 = (tid & 3) * 4;
            float4 v = make_float4(0.f, 0.f, 0.f, 0.f);
            if (k0 + c4 < K)
                v = *reinterpret_cast<const float4*>(Bm + (size_t)(n_blk + n) * K + k0 + c4);
            Bs[c4 + 0][n] = v.x;
            Bs[c4 + 1][n] = v.y;
            Bs[c4 + 2][n] = v.z;
            Bs[c4 + 3][n] = v.w;
        } else {
            int kk = tid >> 4;
            int nn = (tid & 15) * 4;
            float4 v = make_float4(0.f, 0.f, 0.f, 0.f);
            if (k0 + kk < K)
                v = *reinterpret_cast<const float4*>(Bm + (size_t)(k0 + kk) * N + n_blk + nn);
            *reinterpret_cast<float4*>(&Bs[kk][nn]) = v;
        }
        __syncthreads();

#pragma unroll
        for (int kk = 0; kk < GBK; kk++) {
            const ulonglong2* ap = reinterpret_cast<const ulonglong2*>(&As[kk][m0]);
            ulonglong2 aA = ap[0];
            ulonglong2 aB = ap[1];
            float4 b4 = *reinterpret_cast<const float4*>(&Bs[kk][n0]);
            unsigned long long bd[4] = {dup2(b4.x), dup2(b4.y), dup2(b4.z), dup2(b4.w)};
            unsigned long long P[4] = {aA.x, aA.y, aB.x, aB.y};
#pragma unroll
            for (int p = 0; p < 4; p++)
#pragma unroll
                for (int j = 0; j < 4; j++) fma2(acc2[p][j], P[p], bd[j]);
        }
        __syncthreads();
    }

    float bv[4] = {0.f, 0.f, 0.f, 0.f};
    if (bias0) {
#pragma unroll
        for (int j = 0; j < 4; j++) bv[j] += bias0[n_blk + n0 + j];
    }
    if (bias1) {
#pragma unroll
        for (int j = 0; j < 4; j++) bv[j] += bias1[n_blk + n0 + j];
    }
#pragma unroll
    for (int p = 0; p < 4; p++) {
        float2 r0 = unpack2(acc2[p][0]);
        float2 r1 = unpack2(acc2[p][1]);
        float2 r2 = unpack2(acc2[p][2]);
        float2 r3 = unpack2(acc2[p][3]);
        float4 oA = make_float4(r0.x + bv[0], r1.x + bv[1], r2.x + bv[2], r3.x + bv[3]);
        float4 oB = make_float4(r0.y + bv[0], r1.y + bv[1], r2.y + bv[2], r3.y + bv[3]);
        *reinterpret_cast<float4*>(C + (size_t)(m_blk + m0 + 2 * p) * N + n_blk + n0)     = oA;
        *reinterpret_cast<float4*>(C + (size_t)(m_blk + m0 + 2 * p + 1) * N + n_blk + n0) = oB;
    }
}

// ---------------- init recurrent state + barrier counters ----------------
__global__ void init_state_kernel(const float* __restrict__ h01, const float* __restrict__ c01,
                                  const float* __restrict__ h02, const float* __restrict__ c02)
{
    int i = blockIdx.x * blockDim.x + threadIdx.x;
    if (i < 16) g_cnt[i] = 0;
    if (i >= B_ * H_) return;
    g_hbuf[(0 * 2 + 0) * B_ * H_ + i] = h01[i];
    g_cbuf[(0 * 2 + 0) * B_ * H_ + i] = c01[i];
    g_hbuf[(1 * 2 + 0) * B_ * H_ + i] = h02[i];
    g_cbuf[(1 * 2 + 0) * B_ * H_ + i] = c02[i];
}

// ---------------- persistent LSTM scan (R3 structure; fence-free barrier) ----------------
#define WJT 32
#define HS_STRIDE 260
#define SCAN_SMEM ((5 * WJT * 256 + 2 * 16 * HS_STRIDE) * 4)

__global__ __launch_bounds__(256) void lstm_scan_kernel(
    const float* __restrict__ Wall1, const float* __restrict__ Wd1, const float* __restrict__ Wdb1,
    const float* __restrict__ Wall2, const float* __restrict__ Wd2, const float* __restrict__ Wdb2,
    const float* __restrict__ tsp)
{
    extern __shared__ float sm[];
    float* wsm = sm;
    float* hsm = sm + 5 * WJT * 256;
    float* csm = hsm + 16 * HS_STRIDE;

    const int bid   = blockIdx.x;
    const int lstm  = bid >> 6;
    const int btile = (bid >> 3) & 7;
    const int jt    = bid & 7;
    const int b0 = btile * 16;
    const int j0 = jt * WJT;
    const int grp = lstm * 8 + btile;

    const float* Wall = lstm ? Wall2 : Wall1;
    const float* Wd   = lstm ? Wd2   : Wd1;
    const float* Wdb  = lstm ? Wdb2  : Wdb1;
    const float* ux   = lstm ? g_ux2 : g_ux1;
    float*       outp = lstm ? g_out2 : g_out1;

    const int tid = threadIdx.x;

    for (int idx = tid; idx < 5 * WJT * 64; idx += 256) {
        int g   = idx >> 11;
        int rem = idx & 2047;
        int lj  = rem >> 6;
        int k4  = (rem & 63) << 2;
        const float* src = (g < 4) ? (Wall + (size_t)(g * H_ + j0 + lj) * H_ + k4)
                                   : (Wd   + (size_t)(j0 + lj) * H_ + k4);
        *reinterpret_cast<float4*>(&wsm[((g << 5) + lj) * 256 + k4]) =
            *reinterpret_cast<const float4*>(src);
    }

    const int bi = tid & 15;
    const int jj = tid >> 4;
    const int b  = b0 + bi;
    const int jA = j0 + jj;
    const int jB = jA + 16;
    const float wdbA = Wdb[jA];
    const float wdbB = Wdb[jB];

    const float* wA[5];
    const float* wB[5];
#pragma unroll
    for (int g = 0; g < 5; g++) {
        wA[g] = &wsm[((g << 5) + jj) * 256];
        wB[g] = &wsm[((g << 5) + jj + 16) * 256];
    }

    for (int s = 0; s < SEQ_; s++) {
        const int pr = s & 1;
        const float* hsrc = g_hbuf + (size_t)(lstm * 2 + pr) * B_ * H_;
        const float* csrc = g_cbuf + (size_t)(lstm * 2 + pr) * B_ * H_;
        for (int idx = tid; idx < 16 * 64; idx += 256) {
            int r  = idx >> 6;
            int c4 = (idx & 63) << 2;
            *reinterpret_cast<float4*>(&hsm[r * HS_STRIDE + c4]) =
                *reinterpret_cast<const float4*>(&hsrc[(size_t)(b0 + r) * H_ + c4]);
            *reinterpret_cast<float4*>(&csm[r * HS_STRIDE + c4]) =
                *reinterpret_cast<const float4*>(&csrc[(size_t)(b0 + r) * H_ + c4]);
        }
        __syncthreads();

        const size_t row = (size_t)b * SEQ_ + s;
        const float t = tsp[row];
        const float* uxp = ux + row * G4H;
        float uxA[4], uxB[4];
#pragma unroll
        for (int g = 0; g < 4; g++) { uxA[g] = uxp[g * H_ + jA]; uxB[g] = uxp[g * H_ + jB]; }

        unsigned long long acc[10];
#pragma unroll
        for (int i = 0; i < 10; i++) acc[i] = 0ULL;
        const float* hrow = &hsm[bi * HS_STRIDE];
        const float* crow = &csm[bi * HS_STRIDE];

#pragma unroll 4
        for (int k = 0; k < H_; k += 4) {
            ulonglong2 h2 = *reinterpret_cast<const ulonglong2*>(&hrow[k]);
            ulonglong2 c2 = *reinterpret_cast<const ulonglong2*>(&crow[k]);
#pragma unroll
            for (int g = 0; g < 4; g++) {
                ulonglong2 w2 = *reinterpret_cast<const ulonglong2*>(&wA[g][k]);
                fma2(acc[g], h2.x, w2.x);
                fma2(acc[g], h2.y, w2.y);
                ulonglong2 v2 = *reinterpret_cast<const ulonglong2*>(&wB[g][k]);
                fma2(acc[5 + g], h2.x, v2.x);
                fma2(acc[5 + g], h2.y, v2.y);
            }
            ulonglong2 d2 = *reinterpret_cast<const ulonglong2*>(&wA[4][k]);
            fma2(acc[4], c2.x, d2.x);
            fma2(acc[4], c2.y, d2.y);
            ulonglong2 e2 = *reinterpret_cast<const ulonglong2*>(&wB[4][k]);
            fma2(acc[9], c2.x, e2.x);
            fma2(acc[9], c2.y, e2.y);
        }

        float* hdst = g_hbuf + (size_t)(lstm * 2 + (1 - pr)) * B_ * H_;
        float* cdst = g_cbuf + (size_t)(lstm * 2 + (1 - pr)) * B_ * H_;
#pragma unroll
        for (int half = 0; half < 2; half++) {
            const int base = half * 5;
            float2 vf = unpack2(acc[base + 0]);
            float2 vi = unpack2(acc[base + 1]);
            float2 vo = unpack2(acc[base + 2]);
            float2 vc = unpack2(acc[base + 3]);
            float2 vd = unpack2(acc[base + 4]);
            const float af = vf.x + vf.y;
            const float ai = vi.x + vi.y;
            const float ao = vo.x + vo.y;
            const float ag = vc.x + vc.y;
            const float ad = vd.x + vd.y;
            const int   j   = half ? jB : jA;
            const float wdb = half ? wdbB : wdbA;
            const float* uxv = half ? uxB : uxA;

            const float cs1  = tanhf(ad + wdb);
            const float ccur = crow[j];
            const float cadj = ccur - cs1 + cs1 * t;
            const float gf = 1.f / (1.f + expf(-(af + uxv[0])));
            const float gi = 1.f / (1.f + expf(-(ai + uxv[1])));
            const float go = 1.f / (1.f + expf(-(ao + uxv[2])));
            const float gc = 1.f / (1.f + expf(-(ag + uxv[3])));
            const float cnew = gf * cadj + gi * gc;
            const float hnew = go * tanhf(cnew);

            hdst[(size_t)b * H_ + j] = hnew;
            cdst[(size_t)b * H_ + j] = cnew;
            outp[row * H_ + j] = hnew;
        }

        // ---- fence-free barrier: release-add + acquire spin (no nanosleep) ----
        if (s + 1 < SEQ_) {
            __syncthreads();                    // all CTA stores issued before arrive
            if (tid == 0) {
                unsigned* cp = &g_cnt[grp];
                asm volatile("red.release.gpu.global.add.u32 [%0], 1;" :: "l"(cp) : "memory");
                const unsigned target = 8u * (unsigned)(s + 1);
                unsigned v;
                do {
                    asm volatile("ld.acquire.gpu.global.u32 %0, [%1];" : "=r"(v) : "l"(cp) : "memory");
                } while (v < target);
            }
            __syncthreads();                    // propagate tid0's acquire to CTA
        }
    }
}

// ---------------- attention softmax ----------------
__global__ void attn_softmax_kernel(const float* __restrict__ wa)
{
    const int b    = blockIdx.x;
    const int tid  = threadIdx.x;
    const int lane = tid & 31;
    const int w    = tid >> 5;
    __shared__ float Es[SEQ_];
    __shared__ float mx, smv;

    for (int s = w; s < SEQ_; s += 8) {
        const float* o = g_out1 + ((size_t)b * SEQ_ + s) * H_;
        float sum = 0.f;
        for (int h = lane; h < H_; h += 32) sum += o[h] * wa[h];
#pragma unroll
        for (int off = 16; off; off >>= 1) sum += __shfl_xor_sync(0xffffffffu, sum, off);
        if (lane == 0) Es[s] = sum;
    }
    __syncthreads();
    if (tid == 0) {
        float m = -1e30f;
        for (int s = 0; s < SEQ_; s++) m = fmaxf(m, Es[s]);
        mx = m;
    }
    __syncthreads();
    if (tid < SEQ_) Es[tid] = expf(Es[tid] - mx);
    __syncthreads();
    if (tid == 0) {
        float t = 0.f;
        for (int s = 0; s < SEQ_; s++) t += Es[s];
        smv = t;
    }
    __syncthreads();
    if (tid < SEQ_) g_alpha[(size_t)b * SEQ_ + tid] = Es[tid] / smv;
}

// ---------------- ctx partials: grid (B_, 4), 50 steps each ----------------
__global__ void ctx_kernel()
{
    const int b = blockIdx.x;
    const int q = blockIdx.y;
    const int d = threadIdx.x;
    float acc = 0.f;
    const int s0 = q * 50;
    for (int s = s0; s < s0 + 50; s++) {
        size_t r = (size_t)b * SEQ_ + s;
        acc += g_embedded[r * D_ + d] * tanhf(g_beta[r * H_ + d]) * g_alpha[r];
    }
    g_ctxp[q][(size_t)b * D_ + d] = acc;
}

// ---------------- output head (sums 4 ctx partials) ----------------
__global__ void out_kernel(const float* __restrict__ Wout, float* __restrict__ out)
{
    const int b = blockIdx.x;
    const int n = threadIdx.x;
    __shared__ float cx[D_];
    for (int d = threadIdx.x; d < D_; d += blockDim.x) {
        size_t i = (size_t)b * D_ + d;
        cx[d] = (g_ctxp[0][i] + g_ctxp[1][i]) + (g_ctxp[2][i] + g_ctxp[3][i]);
    }
    __syncthreads();
    float acc = 0.f;
    const float* wr = Wout + (size_t)n * H_;
#pragma unroll 8
    for (int d = 0; d < D_; d++) acc = fmaf(cx[d], wr[d], acc);
    out[(size_t)b * NCLS_ + n] = acc;
}

// ---------------- host launcher ----------------
extern "C" void kernel_launch(void* const* d_in, const int* in_sizes, int n_in,
                              void* d_out, int out_size)
{
    const float* inputs = (const float*)d_in[0];
    const float* tsp    = (const float*)d_in[1];
    const float* emb    = (const float*)d_in[2];
    const float* Wall1  = (const float*)d_in[3];
    const float* Wall1b = (const float*)d_in[4];
    const float* Uall1  = (const float*)d_in[5];
    const float* Uall1b = (const float*)d_in[6];
    const float* Wd1    = (const float*)d_in[7];
    const float* Wd1b   = (const float*)d_in[8];
    const float* Wall2  = (const float*)d_in[9];
    const float* Wall2b = (const float*)d_in[10];
    const float* Uall2  = (const float*)d_in[11];
    const float* Uall2b = (const float*)d_in[12];
    const float* Wd2    = (const float*)d_in[13];
    const float* Wd2b   = (const float*)d_in[14];
    const float* wa     = (const float*)d_in[15];
    const float* Wb     = (const float*)d_in[16];
    const float* Wout   = (const float*)d_in[17];
    const float* h01    = (const float*)d_in[18];
    const float* c01    = (const float*)d_in[19];
    const float* h02    = (const float*)d_in[20];
    const float* c02    = (const float*)d_in[21];
    float* out = (float*)d_out;

    void *p_emb, *p_ux1, *p_ux2, *p_out2, *p_beta;
    cudaGetSymbolAddress(&p_emb,  g_embedded);
    cudaGetSymbolAddress(&p_ux1,  g_ux1);
    cudaGetSymbolAddress(&p_ux2,  g_ux2);
    cudaGetSymbolAddress(&p_out2, g_out2);
    cudaGetSymbolAddress(&p_beta, g_beta);

    cudaFuncSetAttribute(lstm_scan_kernel,
                         cudaFuncAttributeMaxDynamicSharedMemorySize, SCAN_SMEM);

    const int M = B_ * SEQ_;   // 25600

    // 1) embedded = inputs @ emb
    gemm_kernel<false><<<dim3(D_ / GBN, M / GBM), 256>>>(
        inputs, emb, (float*)p_emb, M, D_, VOCAB_, nullptr, nullptr);

    // 2) ux = embedded @ Uall^T + (Uall_b + Wall_b)
    gemm_kernel<true><<<dim3(G4H / GBN, M / GBM), 256>>>(
        (const float*)p_emb, Uall1, (float*)p_ux1, M, G4H, D_, Uall1b, Wall1b);
    gemm_kernel<true><<<dim3(G4H / GBN, M / GBM), 256>>>(
        (const float*)p_emb, Uall2, (float*)p_ux2, M, G4H, D_, Uall2b, Wall2b);

    // 3) recurrent scan — R3 structure, fence-free spin barrier
    init_state_kernel<<<(B_ * H_ + 255) / 256, 256>>>(h01, c01, h02, c02);
    lstm_scan_kernel<<<128, 256, SCAN_SMEM>>>(Wall1, Wd1, Wd1b, Wall2, Wd2, Wd2b, tsp);

    // 4) attention weights
    attn_softmax_kernel<<<B_, 256>>>(wa);

    // 5) beta = out2 @ Wb^T
    gemm_kernel<true><<<dim3(H_ / GBN, M / GBM), 256>>>(
        (const float*)p_out2, Wb, (float*)p_beta, M, H_, D_, nullptr, nullptr);

    // 6) context partials + output head
    ctx_kernel<<<dim3(B_, 4), 256>>>();
    out_kernel<<<B_, 128>>>(Wout, out);
}

// round 12
// speedup vs baseline: 1.8756x; 1.0089x over previous
#include <cuda_runtime.h>
#include <math.h>
#include <stdint.h>

#define B_    128
#define SEQ_  200
#define VOCAB_ 1400
#define D_    256
#define H_    256
#define NCLS_ 128
#define G4H   1024

// ---------------- scratch (static __device__, no allocations) ----------------
__device__ float g_embedded[B_ * SEQ_ * D_];
__device__ float g_ux1[B_ * SEQ_ * G4H];
__device__ float g_ux2[B_ * SEQ_ * G4H];
__device__ float g_out1[B_ * SEQ_ * H_];
__device__ float g_out2[B_ * SEQ_ * H_];
__device__ float g_beta[B_ * SEQ_ * H_];
__device__ float g_hbuf[2 * 2 * B_ * H_];     // [lstm][parity][b][h]
__device__ float g_cbuf[2 * 2 * B_ * H_];
__device__ float g_alpha[B_ * SEQ_];
__device__ float g_ctxp[4][B_ * D_];          // 4 partial ctx sums
__device__ unsigned g_cnt[16 * 32];           // per-group counters, 128B apart

// ---------------- packed fp32 helpers (sm_103a f32x2 pipe) ----------------
__device__ __forceinline__ void fma2(unsigned long long& d, unsigned long long a, unsigned long long b) {
    asm("fma.rn.f32x2 %0, %1, %2, %0;" : "+l"(d) : "l"(a), "l"(b));
}
__device__ __forceinline__ unsigned long long dup2(float v) {
    unsigned long long r;
    asm("mov.b64 %0, {%1, %1};" : "=l"(r) : "f"(v));
    return r;
}
__device__ __forceinline__ float2 unpack2(unsigned long long v) {
    float2 f;
    asm("mov.b64 {%0, %1}, %2;" : "=f"(f.x), "=f"(f.y) : "l"(v));
    return f;
}

// ---------------- generic fp32 tiled GEMM (R3 verbatim — proven best) ----------------
#define GBM 128
#define GBN 64
#define GBK 16

template <bool BT>
__global__ void gemm_kernel(const float* __restrict__ A, const float* __restrict__ Bm,
                            float* __restrict__ C, int M, int N, int K,
                            const float* __restrict__ bias0, const float* __restrict__ bias1)
{
    __shared__ float As[GBK][GBM + 4];
    __shared__ float Bs[GBK][GBN + 4];

    const int tid   = threadIdx.x;       // 256 threads
    const int m_blk = blockIdx.y * GBM;
    const int n_blk = blockIdx.x * GBN;
    const int tx = tid & 15;
    const int ty = tid >> 4;
    const int m0 = ty * 8;
    const int n0 = tx * 4;

    unsigned long long acc2[4][4];
#pragma unroll
    for (int i = 0; i < 4; i++)
#pragma unroll
        for (int j = 0; j < 4; j++) acc2[i][j] = 0ULL;

    const int a_row = tid >> 2;
    const int a_c4  = (tid & 3) * 4;

    for (int k0 = 0; k0 < K; k0 += GBK) {
#pragma unroll
        for (int r = 0; r < 2; r++) {
            int m = a_row + r * 64;
            float4 v = make_float4(0.f, 0.f, 0.f, 0.f);
            if (k0 + a_c4 < K)
                v = *reinterpret_cast<const float4*>(A + (size_t)(m_blk + m) * K + k0 + a_c4);
            As[a_c4 + 0][m] = v.x;
            As[a_c4 + 1][m] = v.y;
            As[a_c4 + 2][m] = v.z;
            As[a_c4 + 3][m] = v.w;
        }
        if (BT) {
            int n  = tid >> 2;
            int c4 = (tid & 3) * 4;
            float4 v = make_float4(0.f, 0.f, 0.f, 0.f);
            if (k0 + c4 < K)
                v = *reinterpret_cast<const float4*>(Bm + (size_t)(n_blk + n) * K + k0 + c4);
            Bs[c4 + 0][n] = v.x;
            Bs[c4 + 1][n] = v.y;
            Bs[c4 + 2][n] = v.z;
            Bs[c4 + 3][n] = v.w;
        } else {
            int kk = tid >> 4;
            int nn = (tid & 15) * 4;
            float4 v = make_float4(0.f, 0.f, 0.f, 0.f);
            if (k0 + kk < K)
                v = *reinterpret_cast<const float4*>(Bm + (size_t)(k0 + kk) * N + n_blk + nn);
            *reinterpret_cast<float4*>(&Bs[kk][nn]) = v;
        }
        __syncthreads();

#pragma unroll
        for (int kk = 0; kk < GBK; kk++) {
            const ulonglong2* ap = reinterpret_cast<const ulonglong2*>(&As[kk][m0]);
            ulonglong2 aA = ap[0];
            ulonglong2 aB = ap[1];
            float4 b4 = *reinterpret_cast<const float4*>(&Bs[kk][n0]);
            unsigned long long bd[4] = {dup2(b4.x), dup2(b4.y), dup2(b4.z), dup2(b4.w)};
            unsigned long long P[4] = {aA.x, aA.y, aB.x, aB.y};
#pragma unroll
            for (int p = 0; p < 4; p++)
#pragma unroll
                for (int j = 0; j < 4; j++) fma2(acc2[p][j], P[p], bd[j]);
        }
        __syncthreads();
    }

    float bv[4] = {0.f, 0.f, 0.f, 0.f};
    if (bias0) {
#pragma unroll
        for (int j = 0; j < 4; j++) bv[j] += bias0[n_blk + n0 + j];
    }
    if (bias1) {
#pragma unroll
        for (int j = 0; j < 4; j++) bv[j] += bias1[n_blk + n0 + j];
    }
#pragma unroll
    for (int p = 0; p < 4; p++) {
        float2 r0 = unpack2(acc2[p][0]);
        float2 r1 = unpack2(acc2[p][1]);
        float2 r2 = unpack2(acc2[p][2]);
        float2 r3 = unpack2(acc2[p][3]);
        float4 oA = make_float4(r0.x + bv[0], r1.x + bv[1], r2.x + bv[2], r3.x + bv[3]);
        float4 oB = make_float4(r0.y + bv[0], r1.y + bv[1], r2.y + bv[2], r3.y + bv[3]);
        *reinterpret_cast<float4*>(C + (size_t)(m_blk + m0 + 2 * p) * N + n_blk + n0)     = oA;
        *reinterpret_cast<float4*>(C + (size_t)(m_blk + m0 + 2 * p + 1) * N + n_blk + n0) = oB;
    }
}

// ---------------- init recurrent state + barrier counters ----------------
__global__ void init_state_kernel(const float* __restrict__ h01, const float* __restrict__ c01,
                                  const float* __restrict__ h02, const float* __restrict__ c02)
{
    int i = blockIdx.x * blockDim.x + threadIdx.x;
    if (i < 16 * 32) g_cnt[i] = 0;
    if (i >= B_ * H_) return;
    g_hbuf[(0 * 2 + 0) * B_ * H_ + i] = h01[i];
    g_cbuf[(0 * 2 + 0) * B_ * H_ + i] = c01[i];
    g_hbuf[(1 * 2 + 0) * B_ * H_ + i] = h02[i];
    g_cbuf[(1 * 2 + 0) * B_ * H_ + i] = c02[i];
}

// ---------------- persistent LSTM scan (fence-free barrier + ux pipeline) ----------------
#define WJT 32
#define HS_STRIDE 260
#define SCAN_SMEM ((5 * WJT * 256 + 2 * 16 * HS_STRIDE) * 4)

__global__ __launch_bounds__(256) void lstm_scan_kernel(
    const float* __restrict__ Wall1, const float* __restrict__ Wd1, const float* __restrict__ Wdb1,
    const float* __restrict__ Wall2, const float* __restrict__ Wd2, const float* __restrict__ Wdb2,
    const float* __restrict__ tsp)
{
    extern __shared__ float sm[];
    float* wsm = sm;
    float* hsm = sm + 5 * WJT * 256;
    float* csm = hsm + 16 * HS_STRIDE;

    const int bid   = blockIdx.x;
    const int lstm  = bid >> 6;
    const int btile = (bid >> 3) & 7;
    const int jt    = bid & 7;
    const int b0 = btile * 16;
    const int j0 = jt * WJT;
    const int grp = lstm * 8 + btile;

    const float* Wall = lstm ? Wall2 : Wall1;
    const float* Wd   = lstm ? Wd2   : Wd1;
    const float* Wdb  = lstm ? Wdb2  : Wdb1;
    const float* ux   = lstm ? g_ux2 : g_ux1;
    float*       outp = lstm ? g_out2 : g_out1;

    const int tid = threadIdx.x;

    for (int idx = tid; idx < 5 * WJT * 64; idx += 256) {
        int g   = idx >> 11;
        int rem = idx & 2047;
        int lj  = rem >> 6;
        int k4  = (rem & 63) << 2;
        const float* src = (g < 4) ? (Wall + (size_t)(g * H_ + j0 + lj) * H_ + k4)
                                   : (Wd   + (size_t)(j0 + lj) * H_ + k4);
        *reinterpret_cast<float4*>(&wsm[((g << 5) + lj) * 256 + k4]) =
            *reinterpret_cast<const float4*>(src);
    }

    const int bi = tid & 15;
    const int jj = tid >> 4;
    const int b  = b0 + bi;
    const int jA = j0 + jj;
    const int jB = jA + 16;
    const float wdbA = Wdb[jA];
    const float wdbB = Wdb[jB];

    const float* wA[5];
    const float* wB[5];
#pragma unroll
    for (int g = 0; g < 5; g++) {
        wA[g] = &wsm[((g << 5) + jj) * 256];
        wB[g] = &wsm[((g << 5) + jj + 16) * 256];
    }

    // ---- software-pipelined ux/tsp: preload step 0 ----
    float uxA[4], uxB[4], tcur;
    {
        const size_t row0 = (size_t)b * SEQ_;
        const float* uxp = ux + row0 * G4H;
#pragma unroll
        for (int g = 0; g < 4; g++) { uxA[g] = uxp[g * H_ + jA]; uxB[g] = uxp[g * H_ + jB]; }
        tcur = tsp[row0];
    }

    for (int s = 0; s < SEQ_; s++) {
        const int pr = s & 1;
        const float* hsrc = g_hbuf + (size_t)(lstm * 2 + pr) * B_ * H_;
        const float* csrc = g_cbuf + (size_t)(lstm * 2 + pr) * B_ * H_;
        for (int idx = tid; idx < 16 * 64; idx += 256) {
            int r  = idx >> 6;
            int c4 = (idx & 63) << 2;
            *reinterpret_cast<float4*>(&hsm[r * HS_STRIDE + c4]) =
                *reinterpret_cast<const float4*>(&hsrc[(size_t)(b0 + r) * H_ + c4]);
            *reinterpret_cast<float4*>(&csm[r * HS_STRIDE + c4]) =
                *reinterpret_cast<const float4*>(&csrc[(size_t)(b0 + r) * H_ + c4]);
        }
        __syncthreads();

        // issue next step's ux/tsp loads now — they complete under the dot loop
        float nuxA[4], nuxB[4], ntv = 0.f;
        if (s + 1 < SEQ_) {
            const size_t nrow = (size_t)b * SEQ_ + (s + 1);
            const float* nuxp = ux + nrow * G4H;
#pragma unroll
            for (int g = 0; g < 4; g++) { nuxA[g] = nuxp[g * H_ + jA]; nuxB[g] = nuxp[g * H_ + jB]; }
            ntv = tsp[nrow];
        } else {
#pragma unroll
            for (int g = 0; g < 4; g++) { nuxA[g] = 0.f; nuxB[g] = 0.f; }
        }

        const size_t row = (size_t)b * SEQ_ + s;
        unsigned long long acc[10];
#pragma unroll
        for (int i = 0; i < 10; i++) acc[i] = 0ULL;
        const float* hrow = &hsm[bi * HS_STRIDE];
        const float* crow = &csm[bi * HS_STRIDE];

#pragma unroll 4
        for (int k = 0; k < H_; k += 4) {
            ulonglong2 h2 = *reinterpret_cast<const ulonglong2*>(&hrow[k]);
            ulonglong2 c2 = *reinterpret_cast<const ulonglong2*>(&crow[k]);
#pragma unroll
            for (int g = 0; g < 4; g++) {
                ulonglong2 w2 = *reinterpret_cast<const ulonglong2*>(&wA[g][k]);
                fma2(acc[g], h2.x, w2.x);
                fma2(acc[g], h2.y, w2.y);
                ulonglong2 v2 = *reinterpret_cast<const ulonglong2*>(&wB[g][k]);
                fma2(acc[5 + g], h2.x, v2.x);
                fma2(acc[5 + g], h2.y, v2.y);
            }
            ulonglong2 d2 = *reinterpret_cast<const ulonglong2*>(&wA[4][k]);
            fma2(acc[4], c2.x, d2.x);
            fma2(acc[4], c2.y, d2.y);
            ulonglong2 e2 = *reinterpret_cast<const ulonglong2*>(&wB[4][k]);
            fma2(acc[9], c2.x, e2.x);
            fma2(acc[9], c2.y, e2.y);
        }

        float* hdst = g_hbuf + (size_t)(lstm * 2 + (1 - pr)) * B_ * H_;
        float* cdst = g_cbuf + (size_t)(lstm * 2 + (1 - pr)) * B_ * H_;
#pragma unroll
        for (int half = 0; half < 2; half++) {
            const int base = half * 5;
            float2 vf = unpack2(acc[base + 0]);
            float2 vi = unpack2(acc[base + 1]);
            float2 vo = unpack2(acc[base + 2]);
            float2 vc = unpack2(acc[base + 3]);
            float2 vd = unpack2(acc[base + 4]);
            const float af = vf.x + vf.y;
            const float ai = vi.x + vi.y;
            const float ao = vo.x + vo.y;
            const float ag = vc.x + vc.y;
            const float ad = vd.x + vd.y;
            const int   j   = half ? jB : jA;
            const float wdb = half ? wdbB : wdbA;
            const float* uxv = half ? uxB : uxA;

            const float cs1  = tanhf(ad + wdb);
            const float ccur = crow[j];
            const float cadj = ccur - cs1 + cs1 * tcur;
            const float gf = 1.f / (1.f + expf(-(af + uxv[0])));
            const float gi = 1.f / (1.f + expf(-(ai + uxv[1])));
            const float go = 1.f / (1.f + expf(-(ao + uxv[2])));
            const float gc = 1.f / (1.f + expf(-(ag + uxv[3])));
            const float cnew = gf * cadj + gi * gc;
            const float hnew = go * tanhf(cnew);

            hdst[(size_t)b * H_ + j] = hnew;
            cdst[(size_t)b * H_ + j] = cnew;
            outp[row * H_ + j] = hnew;
        }

        // rotate pipeline registers
#pragma unroll
        for (int g = 0; g < 4; g++) { uxA[g] = nuxA[g]; uxB[g] = nuxB[g]; }
        tcur = ntv;

        // ---- fence-free barrier: release-add + acquire spin (padded counter) ----
        if (s + 1 < SEQ_) {
            __syncthreads();                    // all CTA stores issued before arrive
            if (tid == 0) {
                unsigned* cp = &g_cnt[grp * 32];
                asm volatile("red.release.gpu.global.add.u32 [%0], 1;" :: "l"(cp) : "memory");
                const unsigned target = 8u * (unsigned)(s + 1);
                unsigned v;
                do {
                    asm volatile("ld.acquire.gpu.global.u32 %0, [%1];" : "=r"(v) : "l"(cp) : "memory");
                } while (v < target);
            }
            __syncthreads();                    // propagate tid0's acquire to CTA
        }
    }
}

// ---------------- attention softmax ----------------
__global__ void attn_softmax_kernel(const float* __restrict__ wa)
{
    const int b    = blockIdx.x;
    const int tid  = threadIdx.x;
    const int lane = tid & 31;
    const int w    = tid >> 5;
    __shared__ float Es[SEQ_];
    __shared__ float mx, smv;

    for (int s = w; s < SEQ_; s += 8) {
        const float* o = g_out1 + ((size_t)b * SEQ_ + s) * H_;
        float sum = 0.f;
        for (int h = lane; h < H_; h += 32) sum += o[h] * wa[h];
#pragma unroll
        for (int off = 16; off; off >>= 1) sum += __shfl_xor_sync(0xffffffffu, sum, off);
        if (lane == 0) Es[s] = sum;
    }
    __syncthreads();
    if (tid == 0) {
        float m = -1e30f;
        for (int s = 0; s < SEQ_; s++) m = fmaxf(m, Es[s]);
        mx = m;
    }
    __syncthreads();
    if (tid < SEQ_) Es[tid] = expf(Es[tid] - mx);
    __syncthreads();
    if (tid == 0) {
        float t = 0.f;
        for (int s = 0; s < SEQ_; s++) t += Es[s];
        smv = t;
    }
    __syncthreads();
    if (tid < SEQ_) g_alpha[(size_t)b * SEQ_ + tid] = Es[tid] / smv;
}

// ---------------- ctx partials: grid (B_, 4), 50 steps each ----------------
__global__ void ctx_kernel()
{
    const int b = blockIdx.x;
    const int q = blockIdx.y;
    const int d = threadIdx.x;
    float acc = 0.f;
    const int s0 = q * 50;
    for (int s = s0; s < s0 + 50; s++) {
        size_t r = (size_t)b * SEQ_ + s;
        acc += g_embedded[r * D_ + d] * tanhf(g_beta[r * H_ + d]) * g_alpha[r];
    }
    g_ctxp[q][(size_t)b * D_ + d] = acc;
}

// ---------------- output head (sums 4 ctx partials) ----------------
__global__ void out_kernel(const float* __restrict__ Wout, float* __restrict__ out)
{
    const int b = blockIdx.x;
    const int n = threadIdx.x;
    __shared__ float cx[D_];
    for (int d = threadIdx.x; d < D_; d += blockDim.x) {
        size_t i = (size_t)b * D_ + d;
        cx[d] = (g_ctxp[0][i] + g_ctxp[1][i]) + (g_ctxp[2][i] + g_ctxp[3][i]);
    }
    __syncthreads();
    float acc = 0.f;
    const float* wr = Wout + (size_t)n * H_;
#pragma unroll 8
    for (int d = 0; d < D_; d++) acc = fmaf(cx[d], wr[d], acc);
    out[(size_t)b * NCLS_ + n] = acc;
}

// ---------------- host launcher ----------------
extern "C" void kernel_launch(void* const* d_in, const int* in_sizes, int n_in,
                              void* d_out, int out_size)
{
    const float* inputs = (const float*)d_in[0];
    const float* tsp    = (const float*)d_in[1];
    const float* emb    = (const float*)d_in[2];
    const float* Wall1  = (const float*)d_in[3];
    const float* Wall1b = (const float*)d_in[4];
    const float* Uall1  = (const float*)d_in[5];
    const float* Uall1b = (const float*)d_in[6];
    const float* Wd1    = (const float*)d_in[7];
    const float* Wd1b   = (const float*)d_in[8];
    const float* Wall2  = (const float*)d_in[9];
    const float* Wall2b = (const float*)d_in[10];
    const float* Uall2  = (const float*)d_in[11];
    const float* Uall2b = (const float*)d_in[12];
    const float* Wd2    = (const float*)d_in[13];
    const float* Wd2b   = (const float*)d_in[14];
    const float* wa     = (const float*)d_in[15];
    const float* Wb     = (const float*)d_in[16];
    const float* Wout   = (const float*)d_in[17];
    const float* h01    = (const float*)d_in[18];
    const float* c01    = (const float*)d_in[19];
    const float* h02    = (const float*)d_in[20];
    const float* c02    = (const float*)d_in[21];
    float* out = (float*)d_out;

    void *p_emb, *p_ux1, *p_ux2, *p_out2, *p_beta;
    cudaGetSymbolAddress(&p_emb,  g_embedded);
    cudaGetSymbolAddress(&p_ux1,  g_ux1);
    cudaGetSymbolAddress(&p_ux2,  g_ux2);
    cudaGetSymbolAddress(&p_out2, g_out2);
    cudaGetSymbolAddress(&p_beta, g_beta);

    cudaFuncSetAttribute(lstm_scan_kernel,
                         cudaFuncAttributeMaxDynamicSharedMemorySize, SCAN_SMEM);

    const int M = B_ * SEQ_;   // 25600

    // 1) embedded = inputs @ emb
    gemm_kernel<false><<<dim3(D_ / GBN, M / GBM), 256>>>(
        inputs, emb, (float*)p_emb, M, D_, VOCAB_, nullptr, nullptr);

    // 2) ux = embedded @ Uall^T + (Uall_b + Wall_b)
    gemm_kernel<true><<<dim3(G4H / GBN, M / GBM), 256>>>(
        (const float*)p_emb, Uall1, (float*)p_ux1, M, G4H, D_, Uall1b, Wall1b);
    gemm_kernel<true><<<dim3(G4H / GBN, M / GBM), 256>>>(
        (const float*)p_emb, Uall2, (float*)p_ux2, M, G4H, D_, Uall2b, Wall2b);

    // 3) recurrent scan — fence-free spin barrier (padded) + ux pipeline
    init_state_kernel<<<(B_ * H_ + 255) / 256, 256>>>(h01, c01, h02, c02);
    lstm_scan_kernel<<<128, 256, SCAN_SMEM>>>(Wall1, Wd1, Wd1b, Wall2, Wd2, Wd2b, tsp);

    // 4) attention weights
    attn_softmax_kernel<<<B_, 256>>>(wa);

    // 5) beta = out2 @ Wb^T
    gemm_kernel<true><<<dim3(H_ / GBN, M / GBM), 256>>>(
        (const float*)p_out2, Wb, (float*)p_beta, M, H_, D_, nullptr, nullptr);

    // 6) context partials + output head
    ctx_kernel<<<dim3(B_, 4), 256>>>();
    out_kernel<<<B_, 128>>>(Wout, out);
}

// round 13
// speedup vs baseline: 1.8848x; 1.0049x over previous
#include <cuda_runtime.h>
#include <math.h>
#include <stdint.h>

#define B_    128
#define SEQ_  200
#define VOCAB_ 1400
#define D_    256
#define H_    256
#define NCLS_ 128
#define G4H   1024

// ---------------- scratch (static __device__, no allocations) ----------------
__device__ float g_embedded[B_ * SEQ_ * D_];
__device__ float g_ux1[B_ * SEQ_ * G4H];
__device__ float g_ux2[B_ * SEQ_ * G4H];
__device__ float g_out1[B_ * SEQ_ * H_];
__device__ float g_out2[B_ * SEQ_ * H_];
__device__ float g_beta[B_ * SEQ_ * H_];
__device__ float g_hbuf[2 * 2 * B_ * H_];     // [lstm][parity][b][h]
__device__ float g_cbuf[2 * 2 * B_ * H_];
__device__ float g_alpha[B_ * SEQ_];
__device__ float g_ctxp[4][B_ * D_];          // 4 partial ctx sums
__device__ unsigned g_cnt[16 * 32];           // per-group counters, 128B apart

// ---------------- packed fp32 helpers (sm_103a f32x2 pipe) ----------------
__device__ __forceinline__ void fma2(unsigned long long& d, unsigned long long a, unsigned long long b) {
    asm("fma.rn.f32x2 %0, %1, %2, %0;" : "+l"(d) : "l"(a), "l"(b));
}
__device__ __forceinline__ unsigned long long dup2(float v) {
    unsigned long long r;
    asm("mov.b64 %0, {%1, %1};" : "=l"(r) : "f"(v));
    return r;
}
__device__ __forceinline__ float2 unpack2(unsigned long long v) {
    float2 f;
    asm("mov.b64 {%0, %1}, %2;" : "=f"(f.x), "=f"(f.y) : "l"(v));
    return f;
}

// ---------------- GEMM body (R3-proven), shared by all GEMM kernels ----------------
#define GBM 128
#define GBN 64
#define GBK 16

template <bool BT>
__device__ __forceinline__ void gemm_body(
    const float* __restrict__ A, const float* __restrict__ Bm,
    float* __restrict__ C, int M, int N, int K,
    const float* __restrict__ bias0, const float* __restrict__ bias1)
{
    __shared__ float As[GBK][GBM + 4];
    __shared__ float Bs[GBK][GBN + 4];

    const int tid   = threadIdx.x;       // 256 threads
    const int m_blk = blockIdx.y * GBM;
    const int n_blk = blockIdx.x * GBN;
    const int tx = tid & 15;
    const int ty = tid >> 4;
    const int m0 = ty * 8;
    const int n0 = tx * 4;

    unsigned long long acc2[4][4];
#pragma unroll
    for (int i = 0; i < 4; i++)
#pragma unroll
        for (int j = 0; j < 4; j++) acc2[i][j] = 0ULL;

    const int a_row = tid >> 2;
    const int a_c4  = (tid & 3) * 4;

    for (int k0 = 0; k0 < K; k0 += GBK) {
#pragma unroll
        for (int r = 0; r < 2; r++) {
            int m = a_row + r * 64;
            float4 v = make_float4(0.f, 0.f, 0.f, 0.f);
            if (k0 + a_c4 < K)
                v = *reinterpret_cast<const float4*>(A + (size_t)(m_blk + m) * K + k0 + a_c4);
            As[a_c4 + 0][m] = v.x;
            As[a_c4 + 1][m] = v.y;
            As[a_c4 + 2][m] = v.z;
            As[a_c4 + 3][m] = v.w;
        }
        if (BT) {
            int n  = tid >> 2;
            int c4 = (tid & 3) * 4;
            float4 v = make_float4(0.f, 0.f, 0.f, 0.f);
            if (k0 + c4 < K)
                v = *reinterpret_cast<const float4*>(Bm + (size_t)(n_blk + n) * K + k0 + c4);
            Bs[c4 + 0][n] = v.x;
            Bs[c4 + 1][n] = v.y;
            Bs[c4 + 2][n] = v.z;
            Bs[c4 + 3][n] = v.w;
        } else {
            int kk = tid >> 4;
            int nn = (tid & 15) * 4;
            float4 v = make_float4(0.f, 0.f, 0.f, 0.f);
            if (k0 + kk < K)
                v = *reinterpret_cast<const float4*>(Bm + (size_t)(k0 + kk) * N + n_blk + nn);
            *reinterpret_cast<float4*>(&Bs[kk][nn]) = v;
        }
        __syncthreads();

#pragma unroll
        for (int kk = 0; kk < GBK; kk++) {
            const ulonglong2* ap = reinterpret_cast<const ulonglong2*>(&As[kk][m0]);
            ulonglong2 aA = ap[0];
            ulonglong2 aB = ap[1];
            float4 b4 = *reinterpret_cast<const float4*>(&Bs[kk][n0]);
            unsigned long long bd[4] = {dup2(b4.x), dup2(b4.y), dup2(b4.z), dup2(b4.w)};
            unsigned long long P[4] = {aA.x, aA.y, aB.x, aB.y};
#pragma unroll
            for (int p = 0; p < 4; p++)
#pragma unroll
                for (int j = 0; j < 4; j++) fma2(acc2[p][j], P[p], bd[j]);
        }
        __syncthreads();
    }

    float bv[4] = {0.f, 0.f, 0.f, 0.f};
    if (bias0) {
#pragma unroll
        for (int j = 0; j < 4; j++) bv[j] += bias0[n_blk + n0 + j];
    }
    if (bias1) {
#pragma unroll
        for (int j = 0; j < 4; j++) bv[j] += bias1[n_blk + n0 + j];
    }
#pragma unroll
    for (int p = 0; p < 4; p++) {
        float2 r0 = unpack2(acc2[p][0]);
        float2 r1 = unpack2(acc2[p][1]);
        float2 r2 = unpack2(acc2[p][2]);
        float2 r3 = unpack2(acc2[p][3]);
        float4 oA = make_float4(r0.x + bv[0], r1.x + bv[1], r2.x + bv[2], r3.x + bv[3]);
        float4 oB = make_float4(r0.y + bv[0], r1.y + bv[1], r2.y + bv[2], r3.y + bv[3]);
        *reinterpret_cast<float4*>(C + (size_t)(m_blk + m0 + 2 * p) * N + n_blk + n0)     = oA;
        *reinterpret_cast<float4*>(C + (size_t)(m_blk + m0 + 2 * p + 1) * N + n_blk + n0) = oB;
    }
}

template <bool BT>
__global__ void gemm_kernel(const float* __restrict__ A, const float* __restrict__ Bm,
                            float* __restrict__ C, int M, int N, int K,
                            const float* __restrict__ bias0, const float* __restrict__ bias1)
{
    gemm_body<BT>(A, Bm, C, M, N, K, bias0, bias1);
}

// Fused ux GEMM: blockIdx.z selects lstm 1 vs 2 (same A, different B/bias/out).
__global__ void gemm_ux_kernel(const float* __restrict__ A,
                               const float* __restrict__ U1, const float* __restrict__ U2,
                               const float* __restrict__ u1b, const float* __restrict__ w1b,
                               const float* __restrict__ u2b, const float* __restrict__ w2b,
                               int M, int N, int K)
{
    if (blockIdx.z == 0) {
        gemm_body<true>(A, U1, g_ux1, M, N, K, u1b, w1b);
    } else {
        gemm_body<true>(A, U2, g_ux2, M, N, K, u2b, w2b);
    }
}

// ---------------- init recurrent state + barrier counters ----------------
__global__ void init_state_kernel(const float* __restrict__ h01, const float* __restrict__ c01,
                                  const float* __restrict__ h02, const float* __restrict__ c02)
{
    int i = blockIdx.x * blockDim.x + threadIdx.x;
    if (i < 16 * 32) g_cnt[i] = 0;
    if (i >= B_ * H_) return;
    g_hbuf[(0 * 2 + 0) * B_ * H_ + i] = h01[i];
    g_cbuf[(0 * 2 + 0) * B_ * H_ + i] = c01[i];
    g_hbuf[(1 * 2 + 0) * B_ * H_ + i] = h02[i];
    g_cbuf[(1 * 2 + 0) * B_ * H_ + i] = c02[i];
}

// ---------------- persistent LSTM scan (R12 verbatim — current best) ----------------
#define WJT 32
#define HS_STRIDE 260
#define SCAN_SMEM ((5 * WJT * 256 + 2 * 16 * HS_STRIDE) * 4)

__global__ __launch_bounds__(256) void lstm_scan_kernel(
    const float* __restrict__ Wall1, const float* __restrict__ Wd1, const float* __restrict__ Wdb1,
    const float* __restrict__ Wall2, const float* __restrict__ Wd2, const float* __restrict__ Wdb2,
    const float* __restrict__ tsp)
{
    extern __shared__ float sm[];
    float* wsm = sm;
    float* hsm = sm + 5 * WJT * 256;
    float* csm = hsm + 16 * HS_STRIDE;

    const int bid   = blockIdx.x;
    const int lstm  = bid >> 6;
    const int btile = (bid >> 3) & 7;
    const int jt    = bid & 7;
    const int b0 = btile * 16;
    const int j0 = jt * WJT;
    const int grp = lstm * 8 + btile;

    const float* Wall = lstm ? Wall2 : Wall1;
    const float* Wd   = lstm ? Wd2   : Wd1;
    const float* Wdb  = lstm ? Wdb2  : Wdb1;
    const float* ux   = lstm ? g_ux2 : g_ux1;
    float*       outp = lstm ? g_out2 : g_out1;

    const int tid = threadIdx.x;

    for (int idx = tid; idx < 5 * WJT * 64; idx += 256) {
        int g   = idx >> 11;
        int rem = idx & 2047;
        int lj  = rem >> 6;
        int k4  = (rem & 63) << 2;
        const float* src = (g < 4) ? (Wall + (size_t)(g * H_ + j0 + lj) * H_ + k4)
                                   : (Wd   + (size_t)(j0 + lj) * H_ + k4);
        *reinterpret_cast<float4*>(&wsm[((g << 5) + lj) * 256 + k4]) =
            *reinterpret_cast<const float4*>(src);
    }

    const int bi = tid & 15;
    const int jj = tid >> 4;
    const int b  = b0 + bi;
    const int jA = j0 + jj;
    const int jB = jA + 16;
    const float wdbA = Wdb[jA];
    const float wdbB = Wdb[jB];

    const float* wA[5];
    const float* wB[5];
#pragma unroll
    for (int g = 0; g < 5; g++) {
        wA[g] = &wsm[((g << 5) + jj) * 256];
        wB[g] = &wsm[((g << 5) + jj + 16) * 256];
    }

    // ---- software-pipelined ux/tsp: preload step 0 ----
    float uxA[4], uxB[4], tcur;
    {
        const size_t row0 = (size_t)b * SEQ_;
        const float* uxp = ux + row0 * G4H;
#pragma unroll
        for (int g = 0; g < 4; g++) { uxA[g] = uxp[g * H_ + jA]; uxB[g] = uxp[g * H_ + jB]; }
        tcur = tsp[row0];
    }

    for (int s = 0; s < SEQ_; s++) {
        const int pr = s & 1;
        const float* hsrc = g_hbuf + (size_t)(lstm * 2 + pr) * B_ * H_;
        const float* csrc = g_cbuf + (size_t)(lstm * 2 + pr) * B_ * H_;
        for (int idx = tid; idx < 16 * 64; idx += 256) {
            int r  = idx >> 6;
            int c4 = (idx & 63) << 2;
            *reinterpret_cast<float4*>(&hsm[r * HS_STRIDE + c4]) =
                *reinterpret_cast<const float4*>(&hsrc[(size_t)(b0 + r) * H_ + c4]);
            *reinterpret_cast<float4*>(&csm[r * HS_STRIDE + c4]) =
                *reinterpret_cast<const float4*>(&csrc[(size_t)(b0 + r) * H_ + c4]);
        }
        __syncthreads();

        // issue next step's ux/tsp loads now — they complete under the dot loop
        float nuxA[4], nuxB[4], ntv = 0.f;
        if (s + 1 < SEQ_) {
            const size_t nrow = (size_t)b * SEQ_ + (s + 1);
            const float* nuxp = ux + nrow * G4H;
#pragma unroll
            for (int g = 0; g < 4; g++) { nuxA[g] = nuxp[g * H_ + jA]; nuxB[g] = nuxp[g * H_ + jB]; }
            ntv = tsp[nrow];
        } else {
#pragma unroll
            for (int g = 0; g < 4; g++) { nuxA[g] = 0.f; nuxB[g] = 0.f; }
        }

        const size_t row = (size_t)b * SEQ_ + s;
        unsigned long long acc[10];
#pragma unroll
        for (int i = 0; i < 10; i++) acc[i] = 0ULL;
        const float* hrow = &hsm[bi * HS_STRIDE];
        const float* crow = &csm[bi * HS_STRIDE];

#pragma unroll 4
        for (int k = 0; k < H_; k += 4) {
            ulonglong2 h2 = *reinterpret_cast<const ulonglong2*>(&hrow[k]);
            ulonglong2 c2 = *reinterpret_cast<const ulonglong2*>(&crow[k]);
#pragma unroll
            for (int g = 0; g < 4; g++) {
                ulonglong2 w2 = *reinterpret_cast<const ulonglong2*>(&wA[g][k]);
                fma2(acc[g], h2.x, w2.x);
                fma2(acc[g], h2.y, w2.y);
                ulonglong2 v2 = *reinterpret_cast<const ulonglong2*>(&wB[g][k]);
                fma2(acc[5 + g], h2.x, v2.x);
                fma2(acc[5 + g], h2.y, v2.y);
            }
            ulonglong2 d2 = *reinterpret_cast<const ulonglong2*>(&wA[4][k]);
            fma2(acc[4], c2.x, d2.x);
            fma2(acc[4], c2.y, d2.y);
            ulonglong2 e2 = *reinterpret_cast<const ulonglong2*>(&wB[4][k]);
            fma2(acc[9], c2.x, e2.x);
            fma2(acc[9], c2.y, e2.y);
        }

        float* hdst = g_hbuf + (size_t)(lstm * 2 + (1 - pr)) * B_ * H_;
        float* cdst = g_cbuf + (size_t)(lstm * 2 + (1 - pr)) * B_ * H_;
#pragma unroll
        for (int half = 0; half < 2; half++) {
            const int base = half * 5;
            float2 vf = unpack2(acc[base + 0]);
            float2 vi = unpack2(acc[base + 1]);
            float2 vo = unpack2(acc[base + 2]);
            float2 vc = unpack2(acc[base + 3]);
            float2 vd = unpack2(acc[base + 4]);
            const float af = vf.x + vf.y;
            const float ai = vi.x + vi.y;
            const float ao = vo.x + vo.y;
            const float ag = vc.x + vc.y;
            const float ad = vd.x + vd.y;
            const int   j   = half ? jB : jA;
            const float wdb = half ? wdbB : wdbA;
            const float* uxv = half ? uxB : uxA;

            const float cs1  = tanhf(ad + wdb);
            const float ccur = crow[j];
            const float cadj = ccur - cs1 + cs1 * tcur;
            const float gf = 1.f / (1.f + expf(-(af + uxv[0])));
            const float gi = 1.f / (1.f + expf(-(ai + uxv[1])));
            const float go = 1.f / (1.f + expf(-(ao + uxv[2])));
            const float gc = 1.f / (1.f + expf(-(ag + uxv[3])));
            const float cnew = gf * cadj + gi * gc;
            const float hnew = go * tanhf(cnew);

            hdst[(size_t)b * H_ + j] = hnew;
            cdst[(size_t)b * H_ + j] = cnew;
            outp[row * H_ + j] = hnew;
        }

        // rotate pipeline registers
#pragma unroll
        for (int g = 0; g < 4; g++) { uxA[g] = nuxA[g]; uxB[g] = nuxB[g]; }
        tcur = ntv;

        // ---- fence-free barrier: release-add + acquire spin (padded counter) ----
        if (s + 1 < SEQ_) {
            __syncthreads();                    // all CTA stores issued before arrive
            if (tid == 0) {
                unsigned* cp = &g_cnt[grp * 32];
                asm volatile("red.release.gpu.global.add.u32 [%0], 1;" :: "l"(cp) : "memory");
                const unsigned target = 8u * (unsigned)(s + 1);
                unsigned v;
                do {
                    asm volatile("ld.acquire.gpu.global.u32 %0, [%1];" : "=r"(v) : "l"(cp) : "memory");
                } while (v < target);
            }
            __syncthreads();                    // propagate tid0's acquire to CTA
        }
    }
}

// ---------------- attention softmax ----------------
__global__ void attn_softmax_kernel(const float* __restrict__ wa)
{
    const int b    = blockIdx.x;
    const int tid  = threadIdx.x;
    const int lane = tid & 31;
    const int w    = tid >> 5;
    __shared__ float Es[SEQ_];
    __shared__ float mx, smv;

    for (int s = w; s < SEQ_; s += 8) {
        const float* o = g_out1 + ((size_t)b * SEQ_ + s) * H_;
        float sum = 0.f;
        for (int h = lane; h < H_; h += 32) sum += o[h] * wa[h];
#pragma unroll
        for (int off = 16; off; off >>= 1) sum += __shfl_xor_sync(0xffffffffu, sum, off);
        if (lane == 0) Es[s] = sum;
    }
    __syncthreads();
    if (tid == 0) {
        float m = -1e30f;
        for (int s = 0; s < SEQ_; s++) m = fmaxf(m, Es[s]);
        mx = m;
    }
    __syncthreads();
    if (tid < SEQ_) Es[tid] = expf(Es[tid] - mx);
    __syncthreads();
    if (tid == 0) {
        float t = 0.f;
        for (int s = 0; s < SEQ_; s++) t += Es[s];
        smv = t;
    }
    __syncthreads();
    if (tid < SEQ_) g_alpha[(size_t)b * SEQ_ + tid] = Es[tid] / smv;
}

// ---------------- ctx partials: grid (B_, 4), 50 steps each ----------------
__global__ void ctx_kernel()
{
    const int b = blockIdx.x;
    const int q = blockIdx.y;
    const int d = threadIdx.x;
    float acc = 0.f;
    const int s0 = q * 50;
    for (int s = s0; s < s0 + 50; s++) {
        size_t r = (size_t)b * SEQ_ + s;
        acc += g_embedded[r * D_ + d] * tanhf(g_beta[r * H_ + d]) * g_alpha[r];
    }
    g_ctxp[q][(size_t)b * D_ + d] = acc;
}

// ---------------- output head (sums 4 ctx partials) ----------------
__global__ void out_kernel(const float* __restrict__ Wout, float* __restrict__ out)
{
    const int b = blockIdx.x;
    const int n = threadIdx.x;
    __shared__ float cx[D_];
    for (int d = threadIdx.x; d < D_; d += blockDim.x) {
        size_t i = (size_t)b * D_ + d;
        cx[d] = (g_ctxp[0][i] + g_ctxp[1][i]) + (g_ctxp[2][i] + g_ctxp[3][i]);
    }
    __syncthreads();
    float acc = 0.f;
    const float* wr = Wout + (size_t)n * H_;
#pragma unroll 8
    for (int d = 0; d < D_; d++) acc = fmaf(cx[d], wr[d], acc);
    out[(size_t)b * NCLS_ + n] = acc;
}

// ---------------- host launcher ----------------
extern "C" void kernel_launch(void* const* d_in, const int* in_sizes, int n_in,
                              void* d_out, int out_size)
{
    const float* inputs = (const float*)d_in[0];
    const float* tsp    = (const float*)d_in[1];
    const float* emb    = (const float*)d_in[2];
    const float* Wall1  = (const float*)d_in[3];
    const float* Wall1b = (const float*)d_in[4];
    const float* Uall1  = (const float*)d_in[5];
    const float* Uall1b = (const float*)d_in[6];
    const float* Wd1    = (const float*)d_in[7];
    const float* Wd1b   = (const float*)d_in[8];
    const float* Wall2  = (const float*)d_in[9];
    const float* Wall2b = (const float*)d_in[10];
    const float* Uall2  = (const float*)d_in[11];
    const float* Uall2b = (const float*)d_in[12];
    const float* Wd2    = (const float*)d_in[13];
    const float* Wd2b   = (const float*)d_in[14];
    const float* wa     = (const float*)d_in[15];
    const float* Wb     = (const float*)d_in[16];
    const float* Wout   = (const float*)d_in[17];
    const float* h01    = (const float*)d_in[18];
    const float* c01    = (const float*)d_in[19];
    const float* h02    = (const float*)d_in[20];
    const float* c02    = (const float*)d_in[21];
    float* out = (float*)d_out;

    void *p_emb, *p_out2, *p_beta;
    cudaGetSymbolAddress(&p_emb,  g_embedded);
    cudaGetSymbolAddress(&p_out2, g_out2);
    cudaGetSymbolAddress(&p_beta, g_beta);

    cudaFuncSetAttribute(lstm_scan_kernel,
                         cudaFuncAttributeMaxDynamicSharedMemorySize, SCAN_SMEM);

    const int M = B_ * SEQ_;   // 25600

    // launch 0: init (no deps)
    init_state_kernel<<<(B_ * H_ + 255) / 256, 256>>>(h01, c01, h02, c02);

    // launch 1: embedded = inputs @ emb
    gemm_kernel<false><<<dim3(D_ / GBN, M / GBM), 256>>>(
        inputs, emb, (float*)p_emb, M, D_, VOCAB_, nullptr, nullptr);

    // launch 2: both ux GEMMs fused (z = lstm index)
    gemm_ux_kernel<<<dim3(G4H / GBN, M / GBM, 2), 256>>>(
        (const float*)p_emb, Uall1, Uall2, Uall1b, Wall1b, Uall2b, Wall2b, M, G4H, D_);

    // launch 3: recurrent scan  (ncu capture slot)
    lstm_scan_kernel<<<128, 256, SCAN_SMEM>>>(Wall1, Wd1, Wd1b, Wall2, Wd2, Wd2b, tsp);

    // launch 4: attention weights
    attn_softmax_kernel<<<B_, 256>>>(wa);

    // launch 5: beta = out2 @ Wb^T
    gemm_kernel<true><<<dim3(H_ / GBN, M / GBM), 256>>>(
        (const float*)p_out2, Wb, (float*)p_beta, M, H_, D_, nullptr, nullptr);

    // launches 6-7: context partials + output head
    ctx_kernel<<<dim3(B_, 4), 256>>>();
    out_kernel<<<B_, 128>>>(Wout, out);
}

// round 15
// speedup vs baseline: 2.1040x; 1.1163x over previous
#include <cuda_runtime.h>
#include <math.h>
#include <stdint.h>

#define B_    128
#define SEQ_  200
#define VOCAB_ 1400
#define D_    256
#define H_    256
#define NCLS_ 128
#define G4H   1024

// ---------------- scratch (static __device__, no allocations) ----------------
__device__ float g_embedded[B_ * SEQ_ * D_];
__device__ float g_ux1[B_ * SEQ_ * G4H];
__device__ float g_ux2[B_ * SEQ_ * G4H];
__device__ float g_out1[B_ * SEQ_ * H_];
__device__ float g_out2[B_ * SEQ_ * H_];
__device__ float g_beta[B_ * SEQ_ * H_];
__device__ float g_hbuf[2 * 2 * B_ * H_];     // [lstm][parity][b][h]
__device__ float g_cbuf[2 * 2 * B_ * H_];
__device__ float g_alpha[B_ * SEQ_];
__device__ float g_ctxp[4][B_ * D_];          // 4 partial ctx sums
__device__ unsigned g_cnt[16 * 32];           // per-group counters, 128B apart

// ---------------- packed fp32 helpers (sm_103a f32x2 pipe) ----------------
__device__ __forceinline__ void fma2(unsigned long long& d, unsigned long long a, unsigned long long b) {
    asm("fma.rn.f32x2 %0, %1, %2, %0;" : "+l"(d) : "l"(a), "l"(b));
}
__device__ __forceinline__ unsigned long long dup2(float v) {
    unsigned long long r;
    asm("mov.b64 %0, {%1, %1};" : "=l"(r) : "f"(v));
    return r;
}
__device__ __forceinline__ float2 unpack2(unsigned long long v) {
    float2 f;
    asm("mov.b64 {%0, %1}, %2;" : "=f"(f.x), "=f"(f.y) : "l"(v));
    return f;
}

// ---------------- GEMM body (R3-proven), shared by all GEMM kernels ----------------
#define GBM 128
#define GBN 64
#define GBK 16

template <bool BT>
__device__ __forceinline__ void gemm_body(
    const float* __restrict__ A, const float* __restrict__ Bm,
    float* __restrict__ C, int M, int N, int K,
    const float* __restrict__ bias0, const float* __restrict__ bias1)
{
    __shared__ float As[GBK][GBM + 4];
    __shared__ float Bs[GBK][GBN + 4];

    const int tid   = threadIdx.x;       // 256 threads
    const int m_blk = blockIdx.y * GBM;
    const int n_blk = blockIdx.x * GBN;
    const int tx = tid & 15;
    const int ty = tid >> 4;
    const int m0 = ty * 8;
    const int n0 = tx * 4;

    unsigned long long acc2[4][4];
#pragma unroll
    for (int i = 0; i < 4; i++)
#pragma unroll
        for (int j = 0; j < 4; j++) acc2[i][j] = 0ULL;

    const int a_row = tid >> 2;
    const int a_c4  = (tid & 3) * 4;

    for (int k0 = 0; k0 < K; k0 += GBK) {
#pragma unroll
        for (int r = 0; r < 2; r++) {
            int m = a_row + r * 64;
            float4 v = make_float4(0.f, 0.f, 0.f, 0.f);
            if (k0 + a_c4 < K)
                v = *reinterpret_cast<const float4*>(A + (size_t)(m_blk + m) * K + k0 + a_c4);
            As[a_c4 + 0][m] = v.x;
            As[a_c4 + 1][m] = v.y;
            As[a_c4 + 2][m] = v.z;
            As[a_c4 + 3][m] = v.w;
        }
        if (BT) {
            int n  = tid >> 2;
            int c4 = (tid & 3) * 4;
            float4 v = make_float4(0.f, 0.f, 0.f, 0.f);
            if (k0 + c4 < K)
                v = *reinterpret_cast<const float4*>(Bm + (size_t)(n_blk + n) * K + k0 + c4);
            Bs[c4 + 0][n] = v.x;
            Bs[c4 + 1][n] = v.y;
            Bs[c4 + 2][n] = v.z;
            Bs[c4 + 3][n] = v.w;
        } else {
            int kk = tid >> 4;
            int nn = (tid & 15) * 4;
            float4 v = make_float4(0.f, 0.f, 0.f, 0.f);
            if (k0 + kk < K)
                v = *reinterpret_cast<const float4*>(Bm + (size_t)(k0 + kk) * N + n_blk + nn);
            *reinterpret_cast<float4*>(&Bs[kk][nn]) = v;
        }
        __syncthreads();

#pragma unroll
        for (int kk = 0; kk < GBK; kk++) {
            const ulonglong2* ap = reinterpret_cast<const ulonglong2*>(&As[kk][m0]);
            ulonglong2 aA = ap[0];
            ulonglong2 aB = ap[1];
            float4 b4 = *reinterpret_cast<const float4*>(&Bs[kk][n0]);
            unsigned long long bd[4] = {dup2(b4.x), dup2(b4.y), dup2(b4.z), dup2(b4.w)};
            unsigned long long P[4] = {aA.x, aA.y, aB.x, aB.y};
#pragma unroll
            for (int p = 0; p < 4; p++)
#pragma unroll
                for (int j = 0; j < 4; j++) fma2(acc2[p][j], P[p], bd[j]);
        }
        __syncthreads();
    }

    float bv[4] = {0.f, 0.f, 0.f, 0.f};
    if (bias0) {
#pragma unroll
        for (int j = 0; j < 4; j++) bv[j] += bias0[n_blk + n0 + j];
    }
    if (bias1) {
#pragma unroll
        for (int j = 0; j < 4; j++) bv[j] += bias1[n_blk + n0 + j];
    }
#pragma unroll
    for (int p = 0; p < 4; p++) {
        float2 r0 = unpack2(acc2[p][0]);
        float2 r1 = unpack2(acc2[p][1]);
        float2 r2 = unpack2(acc2[p][2]);
        float2 r3 = unpack2(acc2[p][3]);
        float4 oA = make_float4(r0.x + bv[0], r1.x + bv[1], r2.x + bv[2], r3.x + bv[3]);
        float4 oB = make_float4(r0.y + bv[0], r1.y + bv[1], r2.y + bv[2], r3.y + bv[3]);
        *reinterpret_cast<float4*>(C + (size_t)(m_blk + m0 + 2 * p) * N + n_blk + n0)     = oA;
        *reinterpret_cast<float4*>(C + (size_t)(m_blk + m0 + 2 * p + 1) * N + n_blk + n0) = oB;
    }
}

template <bool BT>
__global__ void gemm_kernel(const float* __restrict__ A, const float* __restrict__ Bm,
                            float* __restrict__ C, int M, int N, int K,
                            const float* __restrict__ bias0, const float* __restrict__ bias1)
{
    gemm_body<BT>(A, Bm, C, M, N, K, bias0, bias1);
}

// Fused ux GEMM: blockIdx.z selects lstm 1 vs 2.
__global__ void gemm_ux_kernel(const float* __restrict__ A,
                               const float* __restrict__ U1, const float* __restrict__ U2,
                               const float* __restrict__ u1b, const float* __restrict__ w1b,
                               const float* __restrict__ u2b, const float* __restrict__ w2b,
                               int M, int N, int K)
{
    if (blockIdx.z == 0) {
        gemm_body<true>(A, U1, g_ux1, M, N, K, u1b, w1b);
    } else {
        gemm_body<true>(A, U2, g_ux2, M, N, K, u2b, w2b);
    }
}

// ---------------- init recurrent state + barrier counters ----------------
__global__ void init_state_kernel(const float* __restrict__ h01, const float* __restrict__ c01,
                                  const float* __restrict__ h02, const float* __restrict__ c02)
{
    int i = blockIdx.x * blockDim.x + threadIdx.x;
    if (i < 16 * 32) g_cnt[i] = 0;
    if (i >= B_ * H_) return;
    g_hbuf[(0 * 2 + 0) * B_ * H_ + i] = h01[i];
    g_cbuf[(0 * 2 + 0) * B_ * H_ + i] = c01[i];
    g_hbuf[(1 * 2 + 0) * B_ * H_ + i] = h02[i];
    g_cbuf[(1 * 2 + 0) * B_ * H_ + i] = c02[i];
}

// ---------------- persistent LSTM scan: bank-deskewed weights, 2bat x 2j x k-half ----------------
// grid = 128 blocks: lstm(2) x btile(8, 16 batches) x jtile(8, 32 h-units). 256 threads.
// Thread: biL = tid&7 (batches biL, biL+8), khalf = (tid>>3)&1 (k half), jp = tid>>4 (j pair).
// Weights staged at row stride 268 with +4-word swizzle on the upper k-half: every weight
// LDS.128 in a warp hits 4 disjoint bank-quads (1 phase). Partner (lane^8) holds the other
// k-half; partials combined with shfl_xor.
#define WJT 32
#define HS_STRIDE 260
#define WSTR 268
#define SCAN_SMEM ((5 * WJT * WSTR + 2 * 16 * HS_STRIDE) * 4)

__global__ __launch_bounds__(256) void lstm_scan_kernel(
    const float* __restrict__ Wall1, const float* __restrict__ Wd1, const float* __restrict__ Wdb1,
    const float* __restrict__ Wall2, const float* __restrict__ Wd2, const float* __restrict__ Wdb2,
    const float* __restrict__ tsp)
{
    extern __shared__ float sm[];
    float* wsm = sm;                           // [5][32][268], k-swizzled
    float* hsm = sm + 5 * WJT * WSTR;          // [16][260]
    float* csm = hsm + 16 * HS_STRIDE;         // [16][260]

    const int bid   = blockIdx.x;
    const int lstm  = bid >> 6;
    const int btile = (bid >> 3) & 7;
    const int jt    = bid & 7;
    const int b0 = btile * 16;
    const int j0 = jt * WJT;
    const int grp = lstm * 8 + btile;

    const float* Wall = lstm ? Wall2 : Wall1;
    const float* Wd   = lstm ? Wd2   : Wd1;
    const float* Wdb  = lstm ? Wdb2  : Wdb1;
    const float* ux   = lstm ? g_ux2 : g_ux1;
    float*       outp = lstm ? g_out2 : g_out1;

    const int tid = threadIdx.x;

    // ---- stage weights once (k-swizzled: col = k + 4*(k>>7)) ----
    for (int idx = tid; idx < 5 * WJT * 64; idx += 256) {
        int g   = idx >> 11;
        int rem = idx & 2047;
        int lj  = rem >> 6;
        int k4  = (rem & 63) << 2;
        int col = k4 + ((k4 >> 7) << 2);
        const float* src = (g < 4) ? (Wall + (size_t)(g * H_ + j0 + lj) * H_ + k4)
                                   : (Wd   + (size_t)(j0 + lj) * H_ + k4);
        *reinterpret_cast<float4*>(&wsm[((g << 5) + lj) * WSTR + col]) =
            *reinterpret_cast<const float4*>(src);
    }

    const int biL   = tid & 7;
    const int khalf = (tid >> 3) & 1;
    const int jp    = tid >> 4;                // 0..15
    const int jA = j0 + 2 * jp;
    const int jB = jA + 1;
    const int biMine = biL + (khalf << 3);
    const int bMine  = b0 + biMine;
    const float wdbA = Wdb[jA];
    const float wdbB = Wdb[jB];

    const float* wbA[5];
    const float* wbB[5];
#pragma unroll
    for (int g = 0; g < 5; g++) {
        const float* base = &wsm[((g << 5) + 2 * jp) * WSTR + khalf * 132];
        wbA[g] = base;
        wbB[g] = base + WSTR;
    }

    const float* hLp = &hsm[biL * HS_STRIDE + khalf * 128];
    const float* hHp = hLp + 8 * HS_STRIDE;
    const float* cLp = &csm[biL * HS_STRIDE + khalf * 128];
    const float* cHp = cLp + 8 * HS_STRIDE;

    // ---- software-pipelined ux/tsp for my batch: preload step 0 ----
    float2 uxv[4];
    float tcur;
    {
        const size_t row0 = (size_t)bMine * SEQ_;
        const float* uxp = ux + row0 * G4H;
#pragma unroll
        for (int g = 0; g < 4; g++)
            uxv[g] = *reinterpret_cast<const float2*>(uxp + g * H_ + jA);
        tcur = tsp[row0];
    }

    for (int s = 0; s < SEQ_; s++) {
        const int pr = s & 1;
        const float* hsrc = g_hbuf + (size_t)(lstm * 2 + pr) * B_ * H_;
        const float* csrc = g_cbuf + (size_t)(lstm * 2 + pr) * B_ * H_;
        for (int idx = tid; idx < 16 * 64; idx += 256) {
            int r  = idx >> 6;
            int c4 = (idx & 63) << 2;
            *reinterpret_cast<float4*>(&hsm[r * HS_STRIDE + c4]) =
                *reinterpret_cast<const float4*>(&hsrc[(size_t)(b0 + r) * H_ + c4]);
            *reinterpret_cast<float4*>(&csm[r * HS_STRIDE + c4]) =
                *reinterpret_cast<const float4*>(&csrc[(size_t)(b0 + r) * H_ + c4]);
        }
        __syncthreads();

        // prefetch next step's ux/tsp (completes under the dot loop)
        float2 nux[4];
        float ntv = 0.f;
        if (s + 1 < SEQ_) {
            const size_t nrow = (size_t)bMine * SEQ_ + (s + 1);
            const float* nuxp = ux + nrow * G4H;
#pragma unroll
            for (int g = 0; g < 4; g++)
                nux[g] = *reinterpret_cast<const float2*>(nuxp + g * H_ + jA);
            ntv = tsp[nrow];
        } else {
#pragma unroll
            for (int g = 0; g < 4; g++) nux[g] = make_float2(0.f, 0.f);
        }

        // ---- dot over my k-half: both batches, both j ----
        unsigned long long aLA[5], aLB[5], aHA[5], aHB[5];
#pragma unroll
        for (int g = 0; g < 5; g++) { aLA[g] = 0ULL; aLB[g] = 0ULL; aHA[g] = 0ULL; aHB[g] = 0ULL; }

#pragma unroll 2
        for (int kk = 0; kk < 128; kk += 4) {
            ulonglong2 h2L = *reinterpret_cast<const ulonglong2*>(&hLp[kk]);
            ulonglong2 h2H = *reinterpret_cast<const ulonglong2*>(&hHp[kk]);
            ulonglong2 c2L = *reinterpret_cast<const ulonglong2*>(&cLp[kk]);
            ulonglong2 c2H = *reinterpret_cast<const ulonglong2*>(&cHp[kk]);
#pragma unroll
            for (int g = 0; g < 4; g++) {
                ulonglong2 wa = *reinterpret_cast<const ulonglong2*>(&wbA[g][kk]);
                ulonglong2 wb = *reinterpret_cast<const ulonglong2*>(&wbB[g][kk]);
                fma2(aLA[g], h2L.x, wa.x); fma2(aLA[g], h2L.y, wa.y);
                fma2(aLB[g], h2L.x, wb.x); fma2(aLB[g], h2L.y, wb.y);
                fma2(aHA[g], h2H.x, wa.x); fma2(aHA[g], h2H.y, wa.y);
                fma2(aHB[g], h2H.x, wb.x); fma2(aHB[g], h2H.y, wb.y);
            }
            ulonglong2 wd = *reinterpret_cast<const ulonglong2*>(&wbA[4][kk]);
            ulonglong2 we = *reinterpret_cast<const ulonglong2*>(&wbB[4][kk]);
            fma2(aLA[4], c2L.x, wd.x); fma2(aLA[4], c2L.y, wd.y);
            fma2(aLB[4], c2L.x, we.x); fma2(aLB[4], c2L.y, we.y);
            fma2(aHA[4], c2H.x, wd.x); fma2(aHA[4], c2H.y, wd.y);
            fma2(aHB[4], c2H.x, we.x); fma2(aHB[4], c2H.y, we.y);
        }

        // ---- collapse to scalars; exchange partner's half for MY batch ----
        float mine[10], theirs[10];
#pragma unroll
        for (int g = 0; g < 5; g++) {
            float2 vLA = unpack2(aLA[g]);
            float2 vLB = unpack2(aLB[g]);
            float2 vHA = unpack2(aHA[g]);
            float2 vHB = unpack2(aHB[g]);
            const float sLA = vLA.x + vLA.y;
            const float sLB = vLB.x + vLB.y;
            const float sHA = vHA.x + vHA.y;
            const float sHB = vHB.x + vHB.y;
            mine[g]       = khalf ? sHA : sLA;     // j = jA, my batch
            mine[5 + g]   = khalf ? sHB : sLB;     // j = jB, my batch
            theirs[g]     = khalf ? sLA : sHA;     // partner's batch
            theirs[5 + g] = khalf ? sLB : sHB;
        }
        float tot[10];
#pragma unroll
        for (int i = 0; i < 10; i++)
            tot[i] = mine[i] + __shfl_xor_sync(0xffffffffu, theirs[i], 8);

        // ---- gate math for my batch, j in {jA, jB} ----
        const size_t rowM = (size_t)bMine * SEQ_ + s;
        float2 cc = *reinterpret_cast<const float2*>(&csm[biMine * HS_STRIDE + jA]);
        float hn[2], cn[2];
#pragma unroll
        for (int half = 0; half < 2; half++) {
            const float af = tot[half * 5 + 0];
            const float ai = tot[half * 5 + 1];
            const float ao = tot[half * 5 + 2];
            const float ag = tot[half * 5 + 3];
            const float ad = tot[half * 5 + 4];
            const float wdb  = half ? wdbB : wdbA;
            const float ccur = half ? cc.y : cc.x;
            const float uf = half ? uxv[0].y : uxv[0].x;
            const float ui = half ? uxv[1].y : uxv[1].x;
            const float uo = half ? uxv[2].y : uxv[2].x;
            const float uc = half ? uxv[3].y : uxv[3].x;

            const float cs1  = tanhf(ad + wdb);
            const float cadj = ccur - cs1 + cs1 * tcur;
            const float gf = 1.f / (1.f + expf(-(af + uf)));
            const float gi = 1.f / (1.f + expf(-(ai + ui)));
            const float go = 1.f / (1.f + expf(-(ao + uo)));
            const float gc = 1.f / (1.f + expf(-(ag + uc)));
            cn[half] = gf * cadj + gi * gc;
            hn[half] = go * tanhf(cn[half]);
        }

        float* hdst = g_hbuf + (size_t)(lstm * 2 + (1 - pr)) * B_ * H_;
        float* cdst = g_cbuf + (size_t)(lstm * 2 + (1 - pr)) * B_ * H_;
        *reinterpret_cast<float2*>(&hdst[(size_t)bMine * H_ + jA]) = make_float2(hn[0], hn[1]);
        *reinterpret_cast<float2*>(&cdst[(size_t)bMine * H_ + jA]) = make_float2(cn[0], cn[1]);
        *reinterpret_cast<float2*>(&outp[rowM * H_ + jA])          = make_float2(hn[0], hn[1]);

        // rotate ux pipeline
#pragma unroll
        for (int g = 0; g < 4; g++) uxv[g] = nux[g];
        tcur = ntv;

        // ---- fence-free barrier: release-add + acquire spin (padded counter) ----
        if (s + 1 < SEQ_) {
            __syncthreads();
            if (tid == 0) {
                unsigned* cp = &g_cnt[grp * 32];
                asm volatile("red.release.gpu.global.add.u32 [%0], 1;" :: "l"(cp) : "memory");
                const unsigned target = 8u * (unsigned)(s + 1);
                unsigned v;
                do {
                    asm volatile("ld.acquire.gpu.global.u32 %0, [%1];" : "=r"(v) : "l"(cp) : "memory");
                } while (v < target);
            }
            __syncthreads();
        }
    }
}

// ---------------- attention softmax ----------------
__global__ void attn_softmax_kernel(const float* __restrict__ wa)
{
    const int b    = blockIdx.x;
    const int tid  = threadIdx.x;
    const int lane = tid & 31;
    const int w    = tid >> 5;
    __shared__ float Es[SEQ_];
    __shared__ float mx, smv;

    for (int s = w; s < SEQ_; s += 8) {
        const float* o = g_out1 + ((size_t)b * SEQ_ + s) * H_;
        float sum = 0.f;
        for (int h = lane; h < H_; h += 32) sum += o[h] * wa[h];
#pragma unroll
        for (int off = 16; off; off >>= 1) sum += __shfl_xor_sync(0xffffffffu, sum, off);
        if (lane == 0) Es[s] = sum;
    }
    __syncthreads();
    if (tid == 0) {
        float m = -1e30f;
        for (int s = 0; s < SEQ_; s++) m = fmaxf(m, Es[s]);
        mx = m;
    }
    __syncthreads();
    if (tid < SEQ_) Es[tid] = expf(Es[tid] - mx);
    __syncthreads();
    if (tid == 0) {
        float t = 0.f;
        for (int s = 0; s < SEQ_; s++) t += Es[s];
        smv = t;
    }
    __syncthreads();
    if (tid < SEQ_) g_alpha[(size_t)b * SEQ_ + tid] = Es[tid] / smv;
}

// ---------------- ctx partials: grid (B_, 4), 50 steps each ----------------
__global__ void ctx_kernel()
{
    const int b = blockIdx.x;
    const int q = blockIdx.y;
    const int d = threadIdx.x;
    float acc = 0.f;
    const int s0 = q * 50;
    for (int s = s0; s < s0 + 50; s++) {
        size_t r = (size_t)b * SEQ_ + s;
        acc += g_embedded[r * D_ + d] * tanhf(g_beta[r * H_ + d]) * g_alpha[r];
    }
    g_ctxp[q][(size_t)b * D_ + d] = acc;
}

// ---------------- output head (sums 4 ctx partials) ----------------
__global__ void out_kernel(const float* __restrict__ Wout, float* __restrict__ out)
{
    const int b = blockIdx.x;
    const int n = threadIdx.x;
    __shared__ float cx[D_];
    for (int d = threadIdx.x; d < D_; d += blockDim.x) {
        size_t i = (size_t)b * D_ + d;
        cx[d] = (g_ctxp[0][i] + g_ctxp[1][i]) + (g_ctxp[2][i] + g_ctxp[3][i]);
    }
    __syncthreads();
    float acc = 0.f;
    const float* wr = Wout + (size_t)n * H_;
#pragma unroll 8
    for (int d = 0; d < D_; d++) acc = fmaf(cx[d], wr[d], acc);
    out[(size_t)b * NCLS_ + n] = acc;
}

// ---------------- host launcher ----------------
extern "C" void kernel_launch(void* const* d_in, const int* in_sizes, int n_in,
                              void* d_out, int out_size)
{
    const float* inputs = (const float*)d_in[0];
    const float* tsp    = (const float*)d_in[1];
    const float* emb    = (const float*)d_in[2];
    const float* Wall1  = (const float*)d_in[3];
    const float* Wall1b = (const float*)d_in[4];
    const float* Uall1  = (const float*)d_in[5];
    const float* Uall1b = (const float*)d_in[6];
    const float* Wd1    = (const float*)d_in[7];
    const float* Wd1b   = (const float*)d_in[8];
    const float* Wall2  = (const float*)d_in[9];
    const float* Wall2b = (const float*)d_in[10];
    const float* Uall2  = (const float*)d_in[11];
    const float* Uall2b = (const float*)d_in[12];
    const float* Wd2    = (const float*)d_in[13];
    const float* Wd2b   = (const float*)d_in[14];
    const float* wa     = (const float*)d_in[15];
    const float* Wb     = (const float*)d_in[16];
    const float* Wout   = (const float*)d_in[17];
    const float* h01    = (const float*)d_in[18];
    const float* c01    = (const float*)d_in[19];
    const float* h02    = (const float*)d_in[20];
    const float* c02    = (const float*)d_in[21];
    float* out = (float*)d_out;

    void *p_emb, *p_out2, *p_beta;
    cudaGetSymbolAddress(&p_emb,  g_embedded);
    cudaGetSymbolAddress(&p_out2, g_out2);
    cudaGetSymbolAddress(&p_beta, g_beta);

    cudaFuncSetAttribute(lstm_scan_kernel,
                         cudaFuncAttributeMaxDynamicSharedMemorySize, SCAN_SMEM);

    const int M = B_ * SEQ_;   // 25600

    // launch 0: init (no deps)
    init_state_kernel<<<(B_ * H_ + 255) / 256, 256>>>(h01, c01, h02, c02);

    // launch 1: embedded = inputs @ emb
    gemm_kernel<false><<<dim3(D_ / GBN, M / GBM), 256>>>(
        inputs, emb, (float*)p_emb, M, D_, VOCAB_, nullptr, nullptr);

    // launch 2: both ux GEMMs fused (z = lstm index)
    gemm_ux_kernel<<<dim3(G4H / GBN, M / GBM, 2), 256>>>(
        (const float*)p_emb, Uall1, Uall2, Uall1b, Wall1b, Uall2b, Wall2b, M, G4H, D_);

    // launch 3: recurrent scan  (ncu capture slot)
    lstm_scan_kernel<<<128, 256, SCAN_SMEM>>>(Wall1, Wd1, Wd1b, Wall2, Wd2, Wd2b, tsp);

    // launch 4: attention weights
    attn_softmax_kernel<<<B_, 256>>>(wa);

    // launch 5: beta = out2 @ Wb^T
    gemm_kernel<true><<<dim3(H_ / GBN, M / GBM), 256>>>(
        (const float*)p_out2, Wb, (float*)p_beta, M, H_, D_, nullptr, nullptr);

    // launches 6-7: context partials + output head
    ctx_kernel<<<dim3(B_, 4), 256>>>();
    out_kernel<<<B_, 128>>>(Wout, out);
}